// round 12
// baseline (speedup 1.0000x reference)
#include <cuda_runtime.h>
#include <math.h>
#include <float.h>

#define B_   2
#define NPTS 2048
#define C_   256
#define KNB  32
#define HID  512
#define CPH  32
#define M1   (B_*NPTS)        // 4096
#define M2   (B_*NPTS*KNB)    // 131072
#define EPSB 1e-5f

#define ST_Q  0
#define ST_K  1
#define ST_V  2
#define ST_PB 3
#define ST_S1 4
#define ST_S2 5
#define ST_M1 6
#define ST_M2 7

#define INV_M1 (1.0/4096.0)
#define INV_M2 (1.0/131072.0)

typedef unsigned long long ull;

// ---------------- device scratch ----------------
__device__ float g_qkv[3*M1*C_];
__device__ float g_tmp4[(size_t)M1*C_*4];
__device__ float g_sqv[M1];
__device__ float g_dist[(size_t)B_*NPTS*NPTS];
__device__ int   g_idx[M2];
__device__ float g_s1[(size_t)M2*CPH];
__device__ float g_s2[(size_t)M2*CPH];
__device__ float g_xattn[M1*C_];
__device__ double g_dsum[8][HID];
__device__ double g_dsum2[8][HID];

__device__ __forceinline__ float lrelu(float z) { return z >= 0.f ? z : 0.2f * z; }

__device__ __forceinline__ void foldco(int stage, int d, double invM,
                                       const float* __restrict__ gamma,
                                       const float* __restrict__ beta,
                                       float& a, float& c)
{
    double m = g_dsum[stage][d] * invM;
    double v = g_dsum2[stage][d] * invM - m * m;
    if (v < 0.0) v = 0.0;
    a = gamma[d] * rsqrtf((float)v + EPSB);
    c = beta[d] - (float)m * a;
}

// ---------------- packed f32x2 helpers ----------------
__device__ __forceinline__ void fma2(ull& d, ull a, ull b) {
    asm("fma.rn.f32x2 %0, %1, %2, %0;" : "+l"(d) : "l"(a), "l"(b));
}
__device__ __forceinline__ ull add2(ull a, ull b) {
    ull d; asm("add.rn.f32x2 %0, %1, %2;" : "=l"(d) : "l"(a), "l"(b)); return d;
}
__device__ __forceinline__ ull mul2(ull a, ull b) {
    ull d; asm("mul.rn.f32x2 %0, %1, %2;" : "=l"(d) : "l"(a), "l"(b)); return d;
}
__device__ __forceinline__ ull dup2(float x) {
    ull r; asm("mov.b64 %0, {%1, %1};" : "=l"(r) : "f"(x)); return r;
}
__device__ __forceinline__ float2 unpk(ull v) {
    float2 f; asm("mov.b64 {%0, %1}, %2;" : "=f"(f.x), "=f"(f.y) : "l"(v)); return f;
}

// quad XOR swizzles
__device__ __forceinline__ int q64(int p) { return p ^ ((p >> 3) & 7); }
__device__ __forceinline__ int q32(int p) { return p ^ (p >> 3); }

// ================= N-packed FMA2 GEMM (R8 version: single buffer, fused stats, dosilu) =================
struct Gemm4 {
    const float* A[4];
    const float* W[4];
    float*       C[4];
    int          stage[4];
};

__global__ __launch_bounds__(256, 2)
void gemm128_kernel(Gemm4 g, int N, int K, int dosilu,
                    const float* __restrict__ fg, const float* __restrict__ fb)
{
    __shared__ __align__(16) float Asd[16][256];   // duplicated A, q64-swizzled quads
    __shared__ __align__(16) float Wt[16][128];    // W, q32-swizzled quads
    __shared__ float sfa[HID], sfc[HID];
    int z = blockIdx.z;
    const float* A = g.A[z];
    const float* W = g.W[z];
    float*       C = g.C[z];
    int stage = g.stage[z];
    int tid = threadIdx.x;

    if (dosilu) {
        for (int d = tid; d < K; d += 256)
            foldco(ST_M1, d, INV_M1, fg, fb, sfa[d], sfc[d]);
        __syncthreads();
    }

    int tx = tid & 15, ty = tid >> 4;
    int m0 = blockIdx.y * 128, n0 = blockIdx.x * 128;
    int lr = tid >> 2;
    int lc = (tid & 3) << 2;

    int af0 = (q64(lr >> 1) << 2) | ((lr & 1) << 1);
    int af1 = (q64((lr + 64) >> 1) << 2) | ((lr & 1) << 1);
    int wf0 = (q32(lr >> 2) << 2) | (lr & 3);
    int wf1 = (q32((lr + 64) >> 2) << 2) | (lr & 3);
    int qa0 = q64(ty * 4 + 0) << 2;
    int qa1 = q64(ty * 4 + 1) << 2;
    int qa2 = q64(ty * 4 + 2) << 2;
    int qa3 = q64(ty * 4 + 3) << 2;
    int qw0 = q32(2 * tx) << 2;
    int qw1 = q32(2 * tx + 1) << 2;

    ull acc[8][4] = {};

    for (int k0 = 0; k0 < K; k0 += 16) {
        float4 a0 = *(const float4*)&A[(size_t)(m0 + lr)      * K + k0 + lc];
        float4 a1 = *(const float4*)&A[(size_t)(m0 + lr + 64) * K + k0 + lc];
        if (dosilu) {
            #pragma unroll
            for (int i = 0; i < 4; i++) {
                float aa = sfa[k0 + lc + i];
                float cc = sfc[k0 + lc + i];
                float* pz = (i==0)?&a0.x:(i==1)?&a0.y:(i==2)?&a0.z:&a0.w;
                float* pw = (i==0)?&a1.x:(i==1)?&a1.y:(i==2)?&a1.z:&a1.w;
                float z0 = aa * (*pz) + cc; *pz = z0 / (1.f + __expf(-z0));
                float z1 = aa * (*pw) + cc; *pw = z1 / (1.f + __expf(-z1));
            }
        }
        float4 w0 = *(const float4*)&W[(size_t)(n0 + lr)      * K + k0 + lc];
        float4 w1 = *(const float4*)&W[(size_t)(n0 + lr + 64) * K + k0 + lc];
        *(ull*)&Asd[lc+0][af0] = dup2(a0.x);
        *(ull*)&Asd[lc+1][af0] = dup2(a0.y);
        *(ull*)&Asd[lc+2][af0] = dup2(a0.z);
        *(ull*)&Asd[lc+3][af0] = dup2(a0.w);
        *(ull*)&Asd[lc+0][af1] = dup2(a1.x);
        *(ull*)&Asd[lc+1][af1] = dup2(a1.y);
        *(ull*)&Asd[lc+2][af1] = dup2(a1.z);
        *(ull*)&Asd[lc+3][af1] = dup2(a1.w);
        Wt[lc+0][wf0] = w0.x; Wt[lc+1][wf0] = w0.y; Wt[lc+2][wf0] = w0.z; Wt[lc+3][wf0] = w0.w;
        Wt[lc+0][wf1] = w1.x; Wt[lc+1][wf1] = w1.y; Wt[lc+2][wf1] = w1.z; Wt[lc+3][wf1] = w1.w;
        __syncthreads();
        #pragma unroll
        for (int kk = 0; kk < 16; kk++) {
            ulonglong2 A0 = *(const ulonglong2*)&Asd[kk][qa0];
            ulonglong2 A1 = *(const ulonglong2*)&Asd[kk][qa1];
            ulonglong2 A2 = *(const ulonglong2*)&Asd[kk][qa2];
            ulonglong2 A3 = *(const ulonglong2*)&Asd[kk][qa3];
            ull ap[8] = { A0.x, A0.y, A1.x, A1.y, A2.x, A2.y, A3.x, A3.y };
            ulonglong2 W0 = *(const ulonglong2*)&Wt[kk][qw0];
            ulonglong2 W1 = *(const ulonglong2*)&Wt[kk][qw1];
            ull wp[4] = { W0.x, W0.y, W1.x, W1.y };
            #pragma unroll
            for (int i = 0; i < 8; i++)
                #pragma unroll
                for (int j = 0; j < 4; j++)
                    fma2(acc[i][j], ap[i], wp[j]);
        }
        __syncthreads();
    }

    #pragma unroll
    for (int i = 0; i < 8; i++) {
        float o[8];
        #pragma unroll
        for (int j = 0; j < 4; j++) {
            float2 p = unpk(acc[i][j]);
            o[2*j] = p.x; o[2*j+1] = p.y;
        }
        size_t r = (size_t)(m0 + ty*8 + i) * N + n0 + tx*8;
        *(float4*)&C[r]     = *(float4*)(o);
        *(float4*)&C[r + 4] = *(float4*)(o + 4);
    }

    if (stage >= 0) {
        float ps[8], ps2[8];
        #pragma unroll
        for (int j = 0; j < 4; j++) {
            ull s = add2(add2(add2(acc[0][j], acc[1][j]), add2(acc[2][j], acc[3][j])),
                         add2(add2(acc[4][j], acc[5][j]), add2(acc[6][j], acc[7][j])));
            ull q = add2(add2(add2(mul2(acc[0][j],acc[0][j]), mul2(acc[1][j],acc[1][j])),
                              add2(mul2(acc[2][j],acc[2][j]), mul2(acc[3][j],acc[3][j]))),
                         add2(add2(mul2(acc[4][j],acc[4][j]), mul2(acc[5][j],acc[5][j])),
                              add2(mul2(acc[6][j],acc[6][j]), mul2(acc[7][j],acc[7][j]))));
            float2 fs = unpk(s), fq = unpk(q);
            ps[2*j] = fs.x; ps[2*j+1] = fs.y;
            ps2[2*j] = fq.x; ps2[2*j+1] = fq.y;
        }
        #pragma unroll
        for (int j = 0; j < 8; j++) {
            ps[j]  += __shfl_down_sync(0xffffffffu, ps[j], 16);
            ps2[j] += __shfl_down_sync(0xffffffffu, ps2[j], 16);
        }
        float (*red)[128] = (float(*)[128])&Asd[0][0];
        int lane = tid & 31, wrp = tid >> 5;
        __syncthreads();
        if (lane < 16) {
            #pragma unroll
            for (int j = 0; j < 8; j++) {
                red[wrp][tx*8 + j]     = ps[j];
                red[wrp + 8][tx*8 + j] = ps2[j];
            }
        }
        __syncthreads();
        if (tid < 128) {
            double s = 0.0, s2 = 0.0;
            #pragma unroll
            for (int w = 0; w < 8; w++) { s += red[w][tid]; s2 += red[w + 8][tid]; }
            atomicAdd(&g_dsum[stage][n0 + tid], s);
            atomicAdd(&g_dsum2[stage][n0 + tid], s2);
        }
    }
}

// ================= symmetric dist, N-packed FMA2, DOUBLE-BUFFERED (the one change) =================
__global__ __launch_bounds__(256, 2)
void dist_kernel(const float* __restrict__ key, const float* __restrict__ sq,
                 float* __restrict__ dist)
{
    int b = blockIdx.z;
    const float* A  = key + (size_t)b * NPTS * C_;
    const float* sb = sq + b * NPTS;
    float* D = dist + (size_t)b * NPTS * NPTS;

    int t = blockIdx.x, bi = 0;
    while (t >= 16 - bi) { t -= 16 - bi; bi++; }
    int bj = bi + t;

    __shared__ __align__(16) float Asd[2][16][256];
    __shared__ __align__(16) float Wt[2][16][128];
    int tid = threadIdx.x;
    int tx = tid & 15, ty = tid >> 4;
    int m0 = bi * 128, n0 = bj * 128;
    int lr = tid >> 2;
    int lc = (tid & 3) << 2;

    int af0 = (q64(lr >> 1) << 2) | ((lr & 1) << 1);
    int af1 = (q64((lr + 64) >> 1) << 2) | ((lr & 1) << 1);
    int wf0 = (q32(lr >> 2) << 2) | (lr & 3);
    int wf1 = (q32((lr + 64) >> 2) << 2) | (lr & 3);
    int qa0 = q64(ty * 4 + 0) << 2;
    int qa1 = q64(ty * 4 + 1) << 2;
    int qa2 = q64(ty * 4 + 2) << 2;
    int qa3 = q64(ty * 4 + 3) << 2;
    int qw0 = q32(2 * tx) << 2;
    int qw1 = q32(2 * tx + 1) << 2;

    ull acc[8][4] = {};
    float4 a0, a1, w0, w1;

    // prologue: tile 0 -> buffer 0
    a0 = *(const float4*)&A[(size_t)(m0 + lr)      * C_ + lc];
    a1 = *(const float4*)&A[(size_t)(m0 + lr + 64) * C_ + lc];
    w0 = *(const float4*)&A[(size_t)(n0 + lr)      * C_ + lc];
    w1 = *(const float4*)&A[(size_t)(n0 + lr + 64) * C_ + lc];
    *(ull*)&Asd[0][lc+0][af0] = dup2(a0.x);
    *(ull*)&Asd[0][lc+1][af0] = dup2(a0.y);
    *(ull*)&Asd[0][lc+2][af0] = dup2(a0.z);
    *(ull*)&Asd[0][lc+3][af0] = dup2(a0.w);
    *(ull*)&Asd[0][lc+0][af1] = dup2(a1.x);
    *(ull*)&Asd[0][lc+1][af1] = dup2(a1.y);
    *(ull*)&Asd[0][lc+2][af1] = dup2(a1.z);
    *(ull*)&Asd[0][lc+3][af1] = dup2(a1.w);
    Wt[0][lc+0][wf0] = w0.x; Wt[0][lc+1][wf0] = w0.y; Wt[0][lc+2][wf0] = w0.z; Wt[0][lc+3][wf0] = w0.w;
    Wt[0][lc+0][wf1] = w1.x; Wt[0][lc+1][wf1] = w1.y; Wt[0][lc+2][wf1] = w1.z; Wt[0][lc+3][wf1] = w1.w;
    __syncthreads();

    const int nT = C_ >> 4;   // 16
    for (int it = 0; it < nT; it++) {
        int cur = it & 1;
        if (it + 1 < nT) {
            int k0 = (it + 1) << 4;
            a0 = *(const float4*)&A[(size_t)(m0 + lr)      * C_ + k0 + lc];
            a1 = *(const float4*)&A[(size_t)(m0 + lr + 64) * C_ + k0 + lc];
            w0 = *(const float4*)&A[(size_t)(n0 + lr)      * C_ + k0 + lc];
            w1 = *(const float4*)&A[(size_t)(n0 + lr + 64) * C_ + k0 + lc];
        }
        #pragma unroll
        for (int kk = 0; kk < 16; kk++) {
            ulonglong2 A0 = *(const ulonglong2*)&Asd[cur][kk][qa0];
            ulonglong2 A1 = *(const ulonglong2*)&Asd[cur][kk][qa1];
            ulonglong2 A2 = *(const ulonglong2*)&Asd[cur][kk][qa2];
            ulonglong2 A3 = *(const ulonglong2*)&Asd[cur][kk][qa3];
            ull ap[8] = { A0.x, A0.y, A1.x, A1.y, A2.x, A2.y, A3.x, A3.y };
            ulonglong2 W0 = *(const ulonglong2*)&Wt[cur][kk][qw0];
            ulonglong2 W1 = *(const ulonglong2*)&Wt[cur][kk][qw1];
            ull wp[4] = { W0.x, W0.y, W1.x, W1.y };
            #pragma unroll
            for (int i = 0; i < 8; i++)
                #pragma unroll
                for (int j = 0; j < 4; j++)
                    fma2(acc[i][j], ap[i], wp[j]);
        }
        if (it + 1 < nT) {
            int nb = cur ^ 1;
            // buffer nb was last read at iteration it-1; all warps passed the
            // barrier at end of it-1 before anyone reaches this store.
            __syncthreads();   // extra safety barrier: all compute on nb finished
            *(ull*)&Asd[nb][lc+0][af0] = dup2(a0.x);
            *(ull*)&Asd[nb][lc+1][af0] = dup2(a0.y);
            *(ull*)&Asd[nb][lc+2][af0] = dup2(a0.z);
            *(ull*)&Asd[nb][lc+3][af0] = dup2(a0.w);
            *(ull*)&Asd[nb][lc+0][af1] = dup2(a1.x);
            *(ull*)&Asd[nb][lc+1][af1] = dup2(a1.y);
            *(ull*)&Asd[nb][lc+2][af1] = dup2(a1.z);
            *(ull*)&Asd[nb][lc+3][af1] = dup2(a1.w);
            Wt[nb][lc+0][wf0] = w0.x; Wt[nb][lc+1][wf0] = w0.y;
            Wt[nb][lc+2][wf0] = w0.z; Wt[nb][lc+3][wf0] = w0.w;
            Wt[nb][lc+0][wf1] = w1.x; Wt[nb][lc+1][wf1] = w1.y;
            Wt[nb][lc+2][wf1] = w1.z; Wt[nb][lc+3][wf1] = w1.w;
            __syncthreads();
        }
    }

    float f[8][8];
    #pragma unroll
    for (int i = 0; i < 8; i++)
        #pragma unroll
        for (int j = 0; j < 4; j++) {
            float2 p = unpk(acc[i][j]);
            f[i][2*j] = p.x; f[i][2*j+1] = p.y;
        }

    float sn[8], sm[8];
    *(float4*)(sn)     = *(const float4*)&sb[n0 + tx*8];
    *(float4*)(sn + 4) = *(const float4*)&sb[n0 + tx*8 + 4];
    *(float4*)(sm)     = *(const float4*)&sb[m0 + ty*8];
    *(float4*)(sm + 4) = *(const float4*)&sb[m0 + ty*8 + 4];

    #pragma unroll
    for (int i = 0; i < 8; i++) {
        float o[8];
        #pragma unroll
        for (int j = 0; j < 8; j++) o[j] = sm[i] + sn[j] - 2.f * f[i][j];
        size_t r = (size_t)(m0 + ty*8 + i) * NPTS + n0 + tx*8;
        *(float4*)&D[r]     = *(float4*)(o);
        *(float4*)&D[r + 4] = *(float4*)(o + 4);
    }
    if (bi != bj) {
        #pragma unroll
        for (int j = 0; j < 8; j++) {
            float o[8];
            #pragma unroll
            for (int i = 0; i < 8; i++) o[i] = sn[j] + sm[i] - 2.f * f[i][j];
            size_t r = (size_t)(n0 + tx*8 + j) * NPTS + m0 + ty*8;
            *(float4*)&D[r]     = *(float4*)(o);
            *(float4*)&D[r + 4] = *(float4*)(o + 4);
        }
    }
}

// ---------------- BN apply q/k/v + fused sq ----------------
__global__ __launch_bounds__(256)
void bnqkv_kernel(const float* __restrict__ Y, float* __restrict__ out,
                  const float* __restrict__ gq, const float* __restrict__ bq,
                  const float* __restrict__ gk, const float* __restrict__ bk,
                  const float* __restrict__ gv, const float* __restrict__ bv,
                  float* __restrict__ sqv)
{
    int blk = blockIdx.x;
    int slice = blk >> 12;
    int row   = blk & 4095;
    int d = threadIdx.x;
    const float* gamma = slice == 0 ? gq : slice == 1 ? gk : gv;
    const float* beta  = slice == 0 ? bq : slice == 1 ? bk : bv;
    float a, c;
    foldco(slice, d, INV_M1, gamma, beta, a, c);
    size_t e = (size_t)blk * 256 + d;
    float z = a * Y[e] + c;
    float o = lrelu(z);
    out[e] = o;

    if (slice == 1) {
        __shared__ float sh[8];
        float s = o * o;
        #pragma unroll
        for (int off = 16; off; off >>= 1) s += __shfl_down_sync(0xffffffffu, s, off);
        if ((d & 31) == 0) sh[d >> 5] = s;
        __syncthreads();
        if (d == 0) {
            float t = 0.f;
            #pragma unroll
            for (int w = 0; w < 8; w++) t += sh[w];
            sqv[row] = t;
        }
    }
}

// ---------------- top-32 ----------------
#define CE(i,j) { if (vr[j] < vr[i] || (vr[j] == vr[i] && idr[j] < idr[i])) { \
                    float tv = vr[i]; vr[i] = vr[j]; vr[j] = tv; \
                    int ti = idr[i]; idr[i] = idr[j]; idr[j] = ti; } }

__global__ __launch_bounds__(256)
void topk_kernel(const float* __restrict__ dist)
{
    int bn = blockIdx.x;
    const float* row = dist + (size_t)bn * NPTS;
    int t = threadIdx.x;
    int lane = t & 31, wrp = t >> 5;

    __shared__ float lv[8][32];
    __shared__ int   li[8][32];

    {
        float vr[8]; int idr[8];
        #pragma unroll
        for (int s = 0; s < 8; s++) {
            int j = wrp * 256 + s * 32 + lane;
            vr[s] = row[j]; idr[s] = j;
        }
        CE(0,1) CE(2,3) CE(4,5) CE(6,7)
        CE(0,2) CE(1,3) CE(4,6) CE(5,7)
        CE(1,2) CE(5,6)
        CE(0,4) CE(1,5) CE(2,6) CE(3,7)
        CE(2,4) CE(3,5)
        CE(1,2) CE(3,4) CE(5,6)

        float outv = FLT_MAX; int outi = 0x7fffffff;
        for (int sel = 0; sel < KNB; sel++) {
            float cv = vr[0]; int ci = idr[0];
            int myhead = idr[0];
            #pragma unroll
            for (int o = 16; o; o >>= 1) {
                float ov = __shfl_xor_sync(0xffffffffu, cv, o);
                int   oi = __shfl_xor_sync(0xffffffffu, ci, o);
                if (ov < cv || (ov == cv && oi < ci)) { cv = ov; ci = oi; }
            }
            if (lane == sel) { outv = cv; outi = ci; }
            if (myhead == ci) {
                #pragma unroll
                for (int s = 0; s < 7; s++) { vr[s] = vr[s+1]; idr[s] = idr[s+1]; }
                vr[7] = FLT_MAX; idr[7] = 0x7fffffff;
            }
        }
        lv[wrp][lane] = outv;
        li[wrp][lane] = outi;
    }
    __syncthreads();

    if (wrp == 0) {
        float vr[8]; int idr[8];
        #pragma unroll
        for (int j = 0; j < 8; j++) { vr[j] = lv[j][lane]; idr[j] = li[j][lane]; }
        CE(0,1) CE(2,3) CE(4,5) CE(6,7)
        CE(0,2) CE(1,3) CE(4,6) CE(5,7)
        CE(1,2) CE(5,6)
        CE(0,4) CE(1,5) CE(2,6) CE(3,7)
        CE(2,4) CE(3,5)
        CE(1,2) CE(3,4) CE(5,6)

        for (int sel = 0; sel < KNB; sel++) {
            float cv = vr[0]; int ci = idr[0];
            int myhead = idr[0];
            #pragma unroll
            for (int o = 16; o; o >>= 1) {
                float ov = __shfl_xor_sync(0xffffffffu, cv, o);
                int   oi = __shfl_xor_sync(0xffffffffu, ci, o);
                if (ov < cv || (ov == cv && oi < ci)) { cv = ov; ci = oi; }
            }
            if (lane == 0) g_idx[(size_t)bn * KNB + sel] = ci;
            if (myhead == ci) {
                #pragma unroll
                for (int s = 0; s < 7; s++) { vr[s] = vr[s+1]; idr[s] = idr[s+1]; }
                vr[7] = FLT_MAX; idr[7] = 0x7fffffff;
            }
        }
    }
}

// ---------------- stats infra ----------------
__global__ void zero_all_stats()
{
    int i = blockIdx.x * 256 + threadIdx.x;
    if (i < 8 * HID) { ((double*)g_dsum)[i] = 0.0; ((double*)g_dsum2)[i] = 0.0; }
}

// ---------------- posb stats via moments ----------------
__global__ __launch_bounds__(256)
void pbstats_kernel(const float* __restrict__ P)
{
    int d = threadIdx.x;
    float s = 0.f, s2 = 0.f;
    for (int gidx = 0; gidx < 16; gidx++) {
        int bn = blockIdx.x * 16 + gidx;
        int b  = bn >> 11;
        float pn = P[(size_t)bn * C_ + d];
        const int* ip = &g_idx[(size_t)bn * KNB];
        float A1 = 0.f, A2 = 0.f;
        #pragma unroll 4
        for (int k = 0; k < KNB; k++) {
            int jg = (b << 11) + ip[k];
            float v = P[(size_t)jg * C_ + d];
            A1 += v; A2 += v * v;
        }
        s  += A1 - 32.f * pn;
        s2 += A2 - 2.f * pn * A1 + 32.f * pn * pn;
    }
    atomicAdd(&g_dsum[ST_PB][d],  (double)s);
    atomicAdd(&g_dsum2[ST_PB][d], (double)s2);
}

// ---------------- final BN+silu+residual ----------------
__global__ void bn_silu_res_apply(const float* __restrict__ Y, const float* __restrict__ res,
                                  float* __restrict__ out,
                                  const float* __restrict__ gm2, const float* __restrict__ bm2)
{
    int d = threadIdx.x;
    float a, c;
    foldco(ST_M2, d, INV_M1, gm2, bm2, a, c);
    size_t e = (size_t)blockIdx.x * 256 + d;
    float z = a * Y[e] + c;
    out[e] = res[e] + z / (1.f + expf(-z));
}

// ---------------- vec1 (R8 version, single buffer) ----------------
__global__ __launch_bounds__(256)
void vec1_kernel(const float* __restrict__ qb, const float* __restrict__ kb,
                 const float* __restrict__ P,  const float* __restrict__ We1,
                 const float* __restrict__ gpb, const float* __restrict__ bpb,
                 float* __restrict__ s1)
{
    __shared__ __align__(16) float As[16][128];
    __shared__ __align__(16) float Wsd[16][64];
    __shared__ __align__(16) float spa[C_], spc[C_];
    __shared__ int sj[128];
    __shared__ float cs[8][32], cs2[8][32];
    int tid = threadIdx.x;
    int m0 = blockIdx.x * 128;
    foldco(ST_PB, tid, INV_M2, gpb, bpb, spa[tid], spc[tid]);
    if (tid < 128) sj[tid] = g_idx[m0 + tid];
    __syncthreads();

    int tx = tid & 15, ty = tid >> 4;
    int lr = tid >> 2;
    int lc = (tid & 3) << 2;
    int r0 = m0 + lr,      bn0 = r0 >> 5, b0 = r0 >> 16;
    int r1 = m0 + lr + 64, bn1 = r1 >> 5, b1 = r1 >> 16;
    int jg0 = (b0 << 11) + sj[lr];
    int jg1 = (b1 << 11) + sj[lr + 64];
    ull acc[4][2] = {};

    for (int k0 = 0; k0 < C_; k0 += 16) {
        #pragma unroll
        for (int h = 0; h < 2; h++) {
            int jg = h ? jg1 : jg0;
            int bn = h ? bn1 : bn0;
            int rr = h ? lr + 64 : lr;
            float4 kf = *(const float4*)&kb[(size_t)jg * C_ + k0 + lc];
            float4 qf = *(const float4*)&qb[(size_t)bn * C_ + k0 + lc];
            float4 pj = *(const float4*)&P [(size_t)jg * C_ + k0 + lc];
            float4 pn = *(const float4*)&P [(size_t)bn * C_ + k0 + lc];
            float4 pa = *(const float4*)&spa[k0 + lc];
            float4 pc = *(const float4*)&spc[k0 + lc];
            As[lc+0][rr] = kf.x - qf.x + lrelu(pa.x * (pj.x - pn.x) + pc.x);
            As[lc+1][rr] = kf.y - qf.y + lrelu(pa.y * (pj.y - pn.y) + pc.y);
            As[lc+2][rr] = kf.z - qf.z + lrelu(pa.z * (pj.z - pn.z) + pc.z);
            As[lc+3][rr] = kf.w - qf.w + lrelu(pa.w * (pj.w - pn.w) + pc.w);
        }
        {
            int i0 = tid;
            *(ull*)&Wsd[i0 >> 5][2*(i0 & 31)] = dup2(We1[(size_t)(i0 & 31) * C_ + k0 + (i0 >> 5)]);
            int i1 = tid + 256;
            *(ull*)&Wsd[i1 >> 5][2*(i1 & 31)] = dup2(We1[(size_t)(i1 & 31) * C_ + k0 + (i1 >> 5)]);
        }
        __syncthreads();
        #pragma unroll
        for (int kk = 0; kk < 16; kk++) {
            ulonglong2 aA = *(const ulonglong2*)&As[kk][ty*8];
            ulonglong2 aB = *(const ulonglong2*)&As[kk][ty*8 + 4];
            ull ap[4] = { aA.x, aA.y, aB.x, aB.y };
            ulonglong2 wv = *(const ulonglong2*)&Wsd[kk][4*tx];
            #pragma unroll
            for (int i2 = 0; i2 < 4; i2++) {
                fma2(acc[i2][0], ap[i2], wv.x);
                fma2(acc[i2][1], ap[i2], wv.y);
            }
        }
        __syncthreads();
    }
    #pragma unroll
    for (int i2 = 0; i2 < 4; i2++) {
        float2 p0 = unpk(acc[i2][0]), p1 = unpk(acc[i2][1]);
        size_t w0 = (size_t)(m0 + ty*8 + 2*i2) * CPH + tx*2;
        s1[w0]           = p0.x; s1[w0 + 1]       = p1.x;
        s1[w0 + CPH]     = p0.y; s1[w0 + CPH + 1] = p1.y;
    }
    float ps[2], ps2[2];
    #pragma unroll
    for (int j = 0; j < 2; j++) {
        ull s = add2(add2(acc[0][j], acc[1][j]), add2(acc[2][j], acc[3][j]));
        ull q = add2(add2(mul2(acc[0][j], acc[0][j]), mul2(acc[1][j], acc[1][j])),
                     add2(mul2(acc[2][j], acc[2][j]), mul2(acc[3][j], acc[3][j])));
        float2 fs = unpk(s), fq = unpk(q);
        ps[j] = fs.x + fs.y; ps2[j] = fq.x + fq.y;
    }
    ps[0]  += __shfl_down_sync(0xffffffffu, ps[0], 16);
    ps[1]  += __shfl_down_sync(0xffffffffu, ps[1], 16);
    ps2[0] += __shfl_down_sync(0xffffffffu, ps2[0], 16);
    ps2[1] += __shfl_down_sync(0xffffffffu, ps2[1], 16);
    int lane = tid & 31, wrp = tid >> 5;
    if (lane < 16) {
        cs[wrp][tx*2]      = ps[0];  cs[wrp][tx*2 + 1]  = ps[1];
        cs2[wrp][tx*2]     = ps2[0]; cs2[wrp][tx*2 + 1] = ps2[1];
    }
    __syncthreads();
    if (tid < 32) {
        double s = 0.0, s2 = 0.0;
        #pragma unroll
        for (int w = 0; w < 8; w++) { s += cs[w][tid]; s2 += cs2[w][tid]; }
        atomicAdd(&g_dsum[ST_S1][tid], s);
        atomicAdd(&g_dsum2[ST_S1][tid], s2);
    }
}

// ---------------- vec2 (R8 version) ----------------
__global__ __launch_bounds__(256)
void vec2_kernel(const float* __restrict__ s1, const float* __restrict__ We2,
                 const float* __restrict__ ge1, const float* __restrict__ be1,
                 float* __restrict__ s2)
{
    __shared__ __align__(16) float As[16][128];
    __shared__ __align__(16) float Wsd[16][64];
    __shared__ __align__(16) float sfa[CPH], sfc[CPH];
    __shared__ float cs[8][32], cs2[8][32];
    int tid = threadIdx.x;
    int m0 = blockIdx.x * 128;
    if (tid < CPH) foldco(ST_S1, tid, INV_M2, ge1, be1, sfa[tid], sfc[tid]);
    __syncthreads();

    int tx = tid & 15, ty = tid >> 4;
    int lr = tid >> 2;
    int lc = (tid & 3) << 2;
    ull acc[4][2] = {};

    for (int k0 = 0; k0 < CPH; k0 += 16) {
        #pragma unroll
        for (int h = 0; h < 2; h++) {
            int rr = h ? lr + 64 : lr;
            float4 y  = *(const float4*)&s1[(size_t)(m0 + rr) * CPH + k0 + lc];
            float4 aa = *(const float4*)&sfa[k0 + lc];
            float4 cc = *(const float4*)&sfc[k0 + lc];
            As[lc+0][rr] = lrelu(aa.x * y.x + cc.x);
            As[lc+1][rr] = lrelu(aa.y * y.y + cc.y);
            As[lc+2][rr] = lrelu(aa.z * y.z + cc.z);
            As[lc+3][rr] = lrelu(aa.w * y.w + cc.w);
        }
        {
            int i0 = tid;
            *(ull*)&Wsd[i0 >> 5][2*(i0 & 31)] = dup2(We2[(size_t)(i0 & 31) * CPH + k0 + (i0 >> 5)]);
            int i1 = tid + 256;
            *(ull*)&Wsd[i1 >> 5][2*(i1 & 31)] = dup2(We2[(size_t)(i1 & 31) * CPH + k0 + (i1 >> 5)]);
        }
        __syncthreads();
        #pragma unroll
        for (int kk = 0; kk < 16; kk++) {
            ulonglong2 aA = *(const ulonglong2*)&As[kk][ty*8];
            ulonglong2 aB = *(const ulonglong2*)&As[kk][ty*8 + 4];
            ull ap[4] = { aA.x, aA.y, aB.x, aB.y };
            ulonglong2 wv = *(const ulonglong2*)&Wsd[kk][4*tx];
            #pragma unroll
            for (int i2 = 0; i2 < 4; i2++) {
                fma2(acc[i2][0], ap[i2], wv.x);
                fma2(acc[i2][1], ap[i2], wv.y);
            }
        }
        __syncthreads();
    }
    #pragma unroll
    for (int i2 = 0; i2 < 4; i2++) {
        float2 p0 = unpk(acc[i2][0]), p1 = unpk(acc[i2][1]);
        size_t w0 = (size_t)(m0 + ty*8 + 2*i2) * CPH + tx*2;
        s2[w0]           = p0.x; s2[w0 + 1]       = p1.x;
        s2[w0 + CPH]     = p0.y; s2[w0 + CPH + 1] = p1.y;
    }
    float ps[2], ps2[2];
    #pragma unroll
    for (int j = 0; j < 2; j++) {
        ull s = add2(add2(acc[0][j], acc[1][j]), add2(acc[2][j], acc[3][j]));
        ull q = add2(add2(mul2(acc[0][j], acc[0][j]), mul2(acc[1][j], acc[1][j])),
                     add2(mul2(acc[2][j], acc[2][j]), mul2(acc[3][j], acc[3][j])));
        float2 fs = unpk(s), fq = unpk(q);
        ps[j] = fs.x + fs.y; ps2[j] = fq.x + fq.y;
    }
    ps[0]  += __shfl_down_sync(0xffffffffu, ps[0], 16);
    ps[1]  += __shfl_down_sync(0xffffffffu, ps[1], 16);
    ps2[0] += __shfl_down_sync(0xffffffffu, ps2[0], 16);
    ps2[1] += __shfl_down_sync(0xffffffffu, ps2[1], 16);
    int lane = tid & 31, wrp = tid >> 5;
    if (lane < 16) {
        cs[wrp][tx*2]      = ps[0];  cs[wrp][tx*2 + 1]  = ps[1];
        cs2[wrp][tx*2]     = ps2[0]; cs2[wrp][tx*2 + 1] = ps2[1];
    }
    __syncthreads();
    if (tid < 32) {
        double s = 0.0, s2 = 0.0;
        #pragma unroll
        for (int w = 0; w < 8; w++) { s += cs[w][tid]; s2 += cs2[w][tid]; }
        atomicAdd(&g_dsum[ST_S2][tid], s);
        atomicAdd(&g_dsum2[ST_S2][tid], s2);
    }
}

// ---------------- attention ----------------
__global__ __launch_bounds__(256)
void attn_kernel(const float* __restrict__ x, const float* __restrict__ s2,
                 const float* __restrict__ vb, const float* __restrict__ P,
                 const float* __restrict__ ge2, const float* __restrict__ be2,
                 const float* __restrict__ gpb, const float* __restrict__ bpb,
                 float* __restrict__ xattn)
{
    int bn = blockIdx.x;
    int t = threadIdx.x;
    __shared__ float soft[KNB][CPH + 1];
    __shared__ float ssa[CPH], ssc[CPH];
    __shared__ int sj[KNB];
    if (t < CPH) foldco(ST_S2, t, INV_M2, ge2, be2, ssa[t], ssc[t]);
    if (t >= 32 && t < 64) sj[t - 32] = g_idx[(size_t)bn * KNB + t - 32];
    float pa, pc;
    foldco(ST_PB, t, INV_M2, gpb, bpb, pa, pc);
    __syncthreads();

    size_t base = (size_t)bn * KNB * CPH;
    for (int e = t; e < KNB * CPH; e += 256) {
        int g = e & 31;
        float y = s2[base + e];
        soft[e >> 5][g] = lrelu(ssa[g] * y + ssc[g]);
    }
    __syncthreads();
    if (t < CPH) {
        float mx = -FLT_MAX;
        #pragma unroll
        for (int k = 0; k < KNB; k++) mx = fmaxf(mx, soft[k][t]);
        float s = 0.f;
        #pragma unroll
        for (int k = 0; k < KNB; k++) { float ev = expf(soft[k][t] - mx); soft[k][t] = ev; s += ev; }
        float inv = 1.f / s;
        #pragma unroll
        for (int k = 0; k < KNB; k++) soft[k][t] *= inv;
    }
    __syncthreads();

    int c = t, g = t >> 3;
    int b = bn >> 11;
    float pn = P[(size_t)bn * C_ + c];
    float acc = 0.f;
    #pragma unroll
    for (int k = 0; k < KNB; k++) {
        int jg = (b << 11) + sj[k];
        float posb = lrelu(pa * (P[(size_t)jg * C_ + c] - pn) + pc);
        acc += (vb[(size_t)jg * C_ + c] + posb) * soft[k][g];
    }
    size_t o = (size_t)bn * C_ + c;
    xattn[o] = x[o] + acc;
}

extern "C" void kernel_launch(void* const* d_in, const int* in_sizes, int n_in,
                              void* d_out, int out_size)
{
    const float* x   = (const float*)d_in[0];
    const float* pos = (const float*)d_in[1];
    const float* Wq  = (const float*)d_in[2];
    const float* gq  = (const float*)d_in[3];
    const float* bq  = (const float*)d_in[4];
    const float* Wk  = (const float*)d_in[5];
    const float* gk  = (const float*)d_in[6];
    const float* bk  = (const float*)d_in[7];
    const float* Wv  = (const float*)d_in[8];
    const float* gv  = (const float*)d_in[9];
    const float* bv  = (const float*)d_in[10];
    const float* Wpb = (const float*)d_in[11];
    const float* gpb = (const float*)d_in[12];
    const float* bpb = (const float*)d_in[13];
    const float* We1 = (const float*)d_in[14];
    const float* ge1 = (const float*)d_in[15];
    const float* be1 = (const float*)d_in[16];
    const float* We2 = (const float*)d_in[17];
    const float* ge2 = (const float*)d_in[18];
    const float* be2 = (const float*)d_in[19];
    const float* Wm1 = (const float*)d_in[20];
    const float* gm1 = (const float*)d_in[21];
    const float* bm1 = (const float*)d_in[22];
    const float* Wm2 = (const float*)d_in[23];
    const float* gm2 = (const float*)d_in[24];
    const float* bm2 = (const float*)d_in[25];
    float* out = (float*)d_out;

    void* p;
    float *qkv, *tmp, *sqv, *dist, *s1, *s2, *xatt;
    cudaGetSymbolAddress(&p, g_qkv);   qkv  = (float*)p;
    cudaGetSymbolAddress(&p, g_tmp4);  tmp  = (float*)p;
    cudaGetSymbolAddress(&p, g_sqv);   sqv  = (float*)p;
    cudaGetSymbolAddress(&p, g_dist);  dist = (float*)p;
    cudaGetSymbolAddress(&p, g_s1);    s1   = (float*)p;
    cudaGetSymbolAddress(&p, g_s2);    s2   = (float*)p;
    cudaGetSymbolAddress(&p, g_xattn); xatt = (float*)p;

    const size_t SL = (size_t)M1 * C_;
    float* t0 = tmp;
    float* t1 = tmp + SL;
    float* t2 = tmp + 2*SL;
    float* t3 = tmp + 3*SL;
    float* qb = qkv;
    float* kb = qkv + SL;
    float* vb = qkv + 2*SL;

    zero_all_stats<<<16, 256>>>();
    {
        Gemm4 g = { { x, x, x, pos }, { Wq, Wk, Wv, Wpb }, { t0, t1, t2, t3 },
                    { ST_Q, ST_K, ST_V, -1 } };
        gemm128_kernel<<<dim3(C_/128, M1/128, 4), 256>>>(g, C_, C_, 0, 0, 0);
    }
    bnqkv_kernel<<<3 * M1, 256>>>(tmp, qkv, gq, bq, gk, bk, gv, bv, sqv);
    dist_kernel<<<dim3(136, 1, B_), 256>>>(kb, sqv, dist);
    topk_kernel<<<M1, 256>>>(dist);
    pbstats_kernel<<<256, 256>>>(t3);
    vec1_kernel<<<M2/128, 256>>>(qb, kb, t3, We1, gpb, bpb, s1);
    vec2_kernel<<<M2/128, 256>>>(s1, We2, ge1, be1, s2);
    attn_kernel<<<M1, 256>>>(x, s2, vb, t3, ge2, be2, gpb, bpb, xatt);
    {
        Gemm4 g = { { xatt, 0, 0, 0 }, { Wm1, 0, 0, 0 }, { t0, 0, 0, 0 },
                    { ST_M1, -1, -1, -1 } };
        gemm128_kernel<<<dim3(HID/128, M1/128, 1), 256>>>(g, HID, C_, 0, 0, 0);
    }
    {
        Gemm4 g = { { t0, 0, 0, 0 }, { Wm2, 0, 0, 0 }, { t2, 0, 0, 0 },
                    { ST_M2, -1, -1, -1 } };
        gemm128_kernel<<<dim3(C_/128, M1/128, 1), 256>>>(g, C_, HID, 1, gm1, bm1);
    }
    bn_silu_res_apply<<<M1, 256>>>(t2, xatt, out, gm2, bm2);
}

// round 13
// speedup vs baseline: 1.0413x; 1.0413x over previous
#include <cuda_runtime.h>
#include <math.h>
#include <float.h>

#define B_   2
#define NPTS 2048
#define C_   256
#define KNB  32
#define HID  512
#define CPH  32
#define M1   (B_*NPTS)        // 4096
#define M2   (B_*NPTS*KNB)    // 131072
#define EPSB 1e-5f

#define ST_Q  0
#define ST_K  1
#define ST_V  2
#define ST_PB 3
#define ST_S1 4
#define ST_S2 5
#define ST_M1 6
#define ST_M2 7

#define INV_M1 (1.0/4096.0)
#define INV_M2 (1.0/131072.0)

typedef unsigned long long ull;

// ---------------- device scratch ----------------
__device__ float g_qkv[3*M1*C_];
__device__ float g_tmp4[(size_t)M1*C_*4];
__device__ float g_sqv[M1];
__device__ float g_dist[(size_t)B_*NPTS*NPTS];
__device__ int   g_idx[M2];
__device__ float g_s1[(size_t)M2*CPH];
__device__ float g_s2[(size_t)M2*CPH];
__device__ float g_xattn[M1*C_];
__device__ double g_dsum[8][HID];
__device__ double g_dsum2[8][HID];

__device__ __forceinline__ float lrelu(float z) { return z >= 0.f ? z : 0.2f * z; }

__device__ __forceinline__ void foldco(int stage, int d, double invM,
                                       const float* __restrict__ gamma,
                                       const float* __restrict__ beta,
                                       float& a, float& c)
{
    double m = g_dsum[stage][d] * invM;
    double v = g_dsum2[stage][d] * invM - m * m;
    if (v < 0.0) v = 0.0;
    a = gamma[d] * rsqrtf((float)v + EPSB);
    c = beta[d] - (float)m * a;
}

// ---------------- packed f32x2 helpers ----------------
__device__ __forceinline__ void fma2(ull& d, ull a, ull b) {
    asm("fma.rn.f32x2 %0, %1, %2, %0;" : "+l"(d) : "l"(a), "l"(b));
}
__device__ __forceinline__ ull add2(ull a, ull b) {
    ull d; asm("add.rn.f32x2 %0, %1, %2;" : "=l"(d) : "l"(a), "l"(b)); return d;
}
__device__ __forceinline__ ull mul2(ull a, ull b) {
    ull d; asm("mul.rn.f32x2 %0, %1, %2;" : "=l"(d) : "l"(a), "l"(b)); return d;
}
__device__ __forceinline__ ull dup2(float x) {
    ull r; asm("mov.b64 %0, {%1, %1};" : "=l"(r) : "f"(x)); return r;
}
__device__ __forceinline__ float2 unpk(ull v) {
    float2 f; asm("mov.b64 {%0, %1}, %2;" : "=f"(f.x), "=f"(f.y) : "l"(v)); return f;
}

// quad XOR swizzles
__device__ __forceinline__ int q64(int p) { return p ^ ((p >> 3) & 7); }
__device__ __forceinline__ int q32(int p) { return p ^ (p >> 3); }

struct Gemm4 {
    const float* A[4];
    const float* W[4];
    float*       C[4];
    int          stage[4];
};

// ================= PIPELINED N-packed FMA2 GEMM (double-barrier schedule, no silu) =================
__global__ __launch_bounds__(256, 2)
void gemm128p_kernel(Gemm4 g, int N, int K)
{
    __shared__ __align__(16) float Asd[2][16][256];   // 32 KB
    __shared__ __align__(16) float Wt[2][16][128];    // 16 KB
    int z = blockIdx.z;
    const float* A = g.A[z];
    const float* W = g.W[z];
    float*       C = g.C[z];
    int stage = g.stage[z];
    int tid = threadIdx.x;

    int tx = tid & 15, ty = tid >> 4;
    int m0 = blockIdx.y * 128, n0 = blockIdx.x * 128;
    int lr = tid >> 2;
    int lc = (tid & 3) << 2;

    int af0 = (q64(lr >> 1) << 2) | ((lr & 1) << 1);
    int af1 = (q64((lr + 64) >> 1) << 2) | ((lr & 1) << 1);
    int wf0 = (q32(lr >> 2) << 2) | (lr & 3);
    int wf1 = (q32((lr + 64) >> 2) << 2) | (lr & 3);
    int qa0 = q64(ty * 4 + 0) << 2;
    int qa1 = q64(ty * 4 + 1) << 2;
    int qa2 = q64(ty * 4 + 2) << 2;
    int qa3 = q64(ty * 4 + 3) << 2;
    int qw0 = q32(2 * tx) << 2;
    int qw1 = q32(2 * tx + 1) << 2;

    ull acc[8][4] = {};
    float4 a0, a1, w0, w1;

    // prologue: tile 0 -> buffer 0
    a0 = *(const float4*)&A[(size_t)(m0 + lr)      * K + lc];
    a1 = *(const float4*)&A[(size_t)(m0 + lr + 64) * K + lc];
    w0 = *(const float4*)&W[(size_t)(n0 + lr)      * K + lc];
    w1 = *(const float4*)&W[(size_t)(n0 + lr + 64) * K + lc];
    *(ull*)&Asd[0][lc+0][af0] = dup2(a0.x);
    *(ull*)&Asd[0][lc+1][af0] = dup2(a0.y);
    *(ull*)&Asd[0][lc+2][af0] = dup2(a0.z);
    *(ull*)&Asd[0][lc+3][af0] = dup2(a0.w);
    *(ull*)&Asd[0][lc+0][af1] = dup2(a1.x);
    *(ull*)&Asd[0][lc+1][af1] = dup2(a1.y);
    *(ull*)&Asd[0][lc+2][af1] = dup2(a1.z);
    *(ull*)&Asd[0][lc+3][af1] = dup2(a1.w);
    Wt[0][lc+0][wf0] = w0.x; Wt[0][lc+1][wf0] = w0.y; Wt[0][lc+2][wf0] = w0.z; Wt[0][lc+3][wf0] = w0.w;
    Wt[0][lc+0][wf1] = w1.x; Wt[0][lc+1][wf1] = w1.y; Wt[0][lc+2][wf1] = w1.z; Wt[0][lc+3][wf1] = w1.w;
    __syncthreads();

    const int nT = K >> 4;
    for (int it = 0; it < nT; it++) {
        int cur = it & 1;
        if (it + 1 < nT) {
            int k0 = (it + 1) << 4;
            a0 = *(const float4*)&A[(size_t)(m0 + lr)      * K + k0 + lc];
            a1 = *(const float4*)&A[(size_t)(m0 + lr + 64) * K + k0 + lc];
            w0 = *(const float4*)&W[(size_t)(n0 + lr)      * K + k0 + lc];
            w1 = *(const float4*)&W[(size_t)(n0 + lr + 64) * K + k0 + lc];
        }
        #pragma unroll
        for (int kk = 0; kk < 16; kk++) {
            ulonglong2 A0 = *(const ulonglong2*)&Asd[cur][kk][qa0];
            ulonglong2 A1 = *(const ulonglong2*)&Asd[cur][kk][qa1];
            ulonglong2 A2 = *(const ulonglong2*)&Asd[cur][kk][qa2];
            ulonglong2 A3 = *(const ulonglong2*)&Asd[cur][kk][qa3];
            ull ap[8] = { A0.x, A0.y, A1.x, A1.y, A2.x, A2.y, A3.x, A3.y };
            ulonglong2 W0 = *(const ulonglong2*)&Wt[cur][kk][qw0];
            ulonglong2 W1 = *(const ulonglong2*)&Wt[cur][kk][qw1];
            ull wp[4] = { W0.x, W0.y, W1.x, W1.y };
            #pragma unroll
            for (int i = 0; i < 8; i++)
                #pragma unroll
                for (int j = 0; j < 4; j++)
                    fma2(acc[i][j], ap[i], wp[j]);
        }
        if (it + 1 < nT) {
            int nb = cur ^ 1;
            __syncthreads();   // all compute on nb finished (proven-safe schedule)
            *(ull*)&Asd[nb][lc+0][af0] = dup2(a0.x);
            *(ull*)&Asd[nb][lc+1][af0] = dup2(a0.y);
            *(ull*)&Asd[nb][lc+2][af0] = dup2(a0.z);
            *(ull*)&Asd[nb][lc+3][af0] = dup2(a0.w);
            *(ull*)&Asd[nb][lc+0][af1] = dup2(a1.x);
            *(ull*)&Asd[nb][lc+1][af1] = dup2(a1.y);
            *(ull*)&Asd[nb][lc+2][af1] = dup2(a1.z);
            *(ull*)&Asd[nb][lc+3][af1] = dup2(a1.w);
            Wt[nb][lc+0][wf0] = w0.x; Wt[nb][lc+1][wf0] = w0.y;
            Wt[nb][lc+2][wf0] = w0.z; Wt[nb][lc+3][wf0] = w0.w;
            Wt[nb][lc+0][wf1] = w1.x; Wt[nb][lc+1][wf1] = w1.y;
            Wt[nb][lc+2][wf1] = w1.z; Wt[nb][lc+3][wf1] = w1.w;
            __syncthreads();
        }
    }

    #pragma unroll
    for (int i = 0; i < 8; i++) {
        float o[8];
        #pragma unroll
        for (int j = 0; j < 4; j++) {
            float2 p = unpk(acc[i][j]);
            o[2*j] = p.x; o[2*j+1] = p.y;
        }
        size_t r = (size_t)(m0 + ty*8 + i) * N + n0 + tx*8;
        *(float4*)&C[r]     = *(float4*)(o);
        *(float4*)&C[r + 4] = *(float4*)(o + 4);
    }

    if (stage >= 0) {
        float ps[8], ps2[8];
        #pragma unroll
        for (int j = 0; j < 4; j++) {
            ull s = add2(add2(add2(acc[0][j], acc[1][j]), add2(acc[2][j], acc[3][j])),
                         add2(add2(acc[4][j], acc[5][j]), add2(acc[6][j], acc[7][j])));
            ull q = add2(add2(add2(mul2(acc[0][j],acc[0][j]), mul2(acc[1][j],acc[1][j])),
                              add2(mul2(acc[2][j],acc[2][j]), mul2(acc[3][j],acc[3][j]))),
                         add2(add2(mul2(acc[4][j],acc[4][j]), mul2(acc[5][j],acc[5][j])),
                              add2(mul2(acc[6][j],acc[6][j]), mul2(acc[7][j],acc[7][j]))));
            float2 fs = unpk(s), fq = unpk(q);
            ps[2*j] = fs.x; ps[2*j+1] = fs.y;
            ps2[2*j] = fq.x; ps2[2*j+1] = fq.y;
        }
        #pragma unroll
        for (int j = 0; j < 8; j++) {
            ps[j]  += __shfl_down_sync(0xffffffffu, ps[j], 16);
            ps2[j] += __shfl_down_sync(0xffffffffu, ps2[j], 16);
        }
        float (*red)[128] = (float(*)[128])&Asd[0][0][0];
        int lane = tid & 31, wrp = tid >> 5;
        __syncthreads();
        if (lane < 16) {
            #pragma unroll
            for (int j = 0; j < 8; j++) {
                red[wrp][tx*8 + j]     = ps[j];
                red[wrp + 8][tx*8 + j] = ps2[j];
            }
        }
        __syncthreads();
        if (tid < 128) {
            double s = 0.0, s2 = 0.0;
            #pragma unroll
            for (int w = 0; w < 8; w++) { s += red[w][tid]; s2 += red[w + 8][tid]; }
            atomicAdd(&g_dsum[stage][n0 + tid], s);
            atomicAdd(&g_dsum2[stage][n0 + tid], s2);
        }
    }
}

// ================= single-buffer gemm (R12 version, dosilu fused) — used for MLP2 only ============
__global__ __launch_bounds__(256, 2)
void gemm128_kernel(Gemm4 g, int N, int K, int dosilu,
                    const float* __restrict__ fg, const float* __restrict__ fb)
{
    __shared__ __align__(16) float Asd[16][256];
    __shared__ __align__(16) float Wt[16][128];
    __shared__ float sfa[HID], sfc[HID];
    int z = blockIdx.z;
    const float* A = g.A[z];
    const float* W = g.W[z];
    float*       C = g.C[z];
    int stage = g.stage[z];
    int tid = threadIdx.x;

    if (dosilu) {
        for (int d = tid; d < K; d += 256)
            foldco(ST_M1, d, INV_M1, fg, fb, sfa[d], sfc[d]);
        __syncthreads();
    }

    int tx = tid & 15, ty = tid >> 4;
    int m0 = blockIdx.y * 128, n0 = blockIdx.x * 128;
    int lr = tid >> 2;
    int lc = (tid & 3) << 2;

    int af0 = (q64(lr >> 1) << 2) | ((lr & 1) << 1);
    int af1 = (q64((lr + 64) >> 1) << 2) | ((lr & 1) << 1);
    int wf0 = (q32(lr >> 2) << 2) | (lr & 3);
    int wf1 = (q32((lr + 64) >> 2) << 2) | (lr & 3);
    int qa0 = q64(ty * 4 + 0) << 2;
    int qa1 = q64(ty * 4 + 1) << 2;
    int qa2 = q64(ty * 4 + 2) << 2;
    int qa3 = q64(ty * 4 + 3) << 2;
    int qw0 = q32(2 * tx) << 2;
    int qw1 = q32(2 * tx + 1) << 2;

    ull acc[8][4] = {};

    for (int k0 = 0; k0 < K; k0 += 16) {
        float4 a0 = *(const float4*)&A[(size_t)(m0 + lr)      * K + k0 + lc];
        float4 a1 = *(const float4*)&A[(size_t)(m0 + lr + 64) * K + k0 + lc];
        if (dosilu) {
            #pragma unroll
            for (int i = 0; i < 4; i++) {
                float aa = sfa[k0 + lc + i];
                float cc = sfc[k0 + lc + i];
                float* pz = (i==0)?&a0.x:(i==1)?&a0.y:(i==2)?&a0.z:&a0.w;
                float* pw = (i==0)?&a1.x:(i==1)?&a1.y:(i==2)?&a1.z:&a1.w;
                float z0 = aa * (*pz) + cc; *pz = z0 / (1.f + __expf(-z0));
                float z1 = aa * (*pw) + cc; *pw = z1 / (1.f + __expf(-z1));
            }
        }
        float4 w0 = *(const float4*)&W[(size_t)(n0 + lr)      * K + k0 + lc];
        float4 w1 = *(const float4*)&W[(size_t)(n0 + lr + 64) * K + k0 + lc];
        *(ull*)&Asd[lc+0][af0] = dup2(a0.x);
        *(ull*)&Asd[lc+1][af0] = dup2(a0.y);
        *(ull*)&Asd[lc+2][af0] = dup2(a0.z);
        *(ull*)&Asd[lc+3][af0] = dup2(a0.w);
        *(ull*)&Asd[lc+0][af1] = dup2(a1.x);
        *(ull*)&Asd[lc+1][af1] = dup2(a1.y);
        *(ull*)&Asd[lc+2][af1] = dup2(a1.z);
        *(ull*)&Asd[lc+3][af1] = dup2(a1.w);
        Wt[lc+0][wf0] = w0.x; Wt[lc+1][wf0] = w0.y; Wt[lc+2][wf0] = w0.z; Wt[lc+3][wf0] = w0.w;
        Wt[lc+0][wf1] = w1.x; Wt[lc+1][wf1] = w1.y; Wt[lc+2][wf1] = w1.z; Wt[lc+3][wf1] = w1.w;
        __syncthreads();
        #pragma unroll
        for (int kk = 0; kk < 16; kk++) {
            ulonglong2 A0 = *(const ulonglong2*)&Asd[kk][qa0];
            ulonglong2 A1 = *(const ulonglong2*)&Asd[kk][qa1];
            ulonglong2 A2 = *(const ulonglong2*)&Asd[kk][qa2];
            ulonglong2 A3 = *(const ulonglong2*)&Asd[kk][qa3];
            ull ap[8] = { A0.x, A0.y, A1.x, A1.y, A2.x, A2.y, A3.x, A3.y };
            ulonglong2 W0 = *(const ulonglong2*)&Wt[kk][qw0];
            ulonglong2 W1 = *(const ulonglong2*)&Wt[kk][qw1];
            ull wp[4] = { W0.x, W0.y, W1.x, W1.y };
            #pragma unroll
            for (int i = 0; i < 8; i++)
                #pragma unroll
                for (int j = 0; j < 4; j++)
                    fma2(acc[i][j], ap[i], wp[j]);
        }
        __syncthreads();
    }

    #pragma unroll
    for (int i = 0; i < 8; i++) {
        float o[8];
        #pragma unroll
        for (int j = 0; j < 4; j++) {
            float2 p = unpk(acc[i][j]);
            o[2*j] = p.x; o[2*j+1] = p.y;
        }
        size_t r = (size_t)(m0 + ty*8 + i) * N + n0 + tx*8;
        *(float4*)&C[r]     = *(float4*)(o);
        *(float4*)&C[r + 4] = *(float4*)(o + 4);
    }

    if (stage >= 0) {
        float ps[8], ps2[8];
        #pragma unroll
        for (int j = 0; j < 4; j++) {
            ull s = add2(add2(add2(acc[0][j], acc[1][j]), add2(acc[2][j], acc[3][j])),
                         add2(add2(acc[4][j], acc[5][j]), add2(acc[6][j], acc[7][j])));
            ull q = add2(add2(add2(mul2(acc[0][j],acc[0][j]), mul2(acc[1][j],acc[1][j])),
                              add2(mul2(acc[2][j],acc[2][j]), mul2(acc[3][j],acc[3][j]))),
                         add2(add2(mul2(acc[4][j],acc[4][j]), mul2(acc[5][j],acc[5][j])),
                              add2(mul2(acc[6][j],acc[6][j]), mul2(acc[7][j],acc[7][j]))));
            float2 fs = unpk(s), fq = unpk(q);
            ps[2*j] = fs.x; ps[2*j+1] = fs.y;
            ps2[2*j] = fq.x; ps2[2*j+1] = fq.y;
        }
        #pragma unroll
        for (int j = 0; j < 8; j++) {
            ps[j]  += __shfl_down_sync(0xffffffffu, ps[j], 16);
            ps2[j] += __shfl_down_sync(0xffffffffu, ps2[j], 16);
        }
        float (*red)[128] = (float(*)[128])&Asd[0][0];
        int lane = tid & 31, wrp = tid >> 5;
        __syncthreads();
        if (lane < 16) {
            #pragma unroll
            for (int j = 0; j < 8; j++) {
                red[wrp][tx*8 + j]     = ps[j];
                red[wrp + 8][tx*8 + j] = ps2[j];
            }
        }
        __syncthreads();
        if (tid < 128) {
            double s = 0.0, s2 = 0.0;
            #pragma unroll
            for (int w = 0; w < 8; w++) { s += red[w][tid]; s2 += red[w + 8][tid]; }
            atomicAdd(&g_dsum[stage][n0 + tid], s);
            atomicAdd(&g_dsum2[stage][n0 + tid], s2);
        }
    }
}

// ================= symmetric dist (R12 version, double-buffered, unchanged) =================
__global__ __launch_bounds__(256, 2)
void dist_kernel(const float* __restrict__ key, const float* __restrict__ sq,
                 float* __restrict__ dist)
{
    int b = blockIdx.z;
    const float* A  = key + (size_t)b * NPTS * C_;
    const float* sb = sq + b * NPTS;
    float* D = dist + (size_t)b * NPTS * NPTS;

    int t = blockIdx.x, bi = 0;
    while (t >= 16 - bi) { t -= 16 - bi; bi++; }
    int bj = bi + t;

    __shared__ __align__(16) float Asd[2][16][256];
    __shared__ __align__(16) float Wt[2][16][128];
    int tid = threadIdx.x;
    int tx = tid & 15, ty = tid >> 4;
    int m0 = bi * 128, n0 = bj * 128;
    int lr = tid >> 2;
    int lc = (tid & 3) << 2;

    int af0 = (q64(lr >> 1) << 2) | ((lr & 1) << 1);
    int af1 = (q64((lr + 64) >> 1) << 2) | ((lr & 1) << 1);
    int wf0 = (q32(lr >> 2) << 2) | (lr & 3);
    int wf1 = (q32((lr + 64) >> 2) << 2) | (lr & 3);
    int qa0 = q64(ty * 4 + 0) << 2;
    int qa1 = q64(ty * 4 + 1) << 2;
    int qa2 = q64(ty * 4 + 2) << 2;
    int qa3 = q64(ty * 4 + 3) << 2;
    int qw0 = q32(2 * tx) << 2;
    int qw1 = q32(2 * tx + 1) << 2;

    ull acc[8][4] = {};
    float4 a0, a1, w0, w1;

    a0 = *(const float4*)&A[(size_t)(m0 + lr)      * C_ + lc];
    a1 = *(const float4*)&A[(size_t)(m0 + lr + 64) * C_ + lc];
    w0 = *(const float4*)&A[(size_t)(n0 + lr)      * C_ + lc];
    w1 = *(const float4*)&A[(size_t)(n0 + lr + 64) * C_ + lc];
    *(ull*)&Asd[0][lc+0][af0] = dup2(a0.x);
    *(ull*)&Asd[0][lc+1][af0] = dup2(a0.y);
    *(ull*)&Asd[0][lc+2][af0] = dup2(a0.z);
    *(ull*)&Asd[0][lc+3][af0] = dup2(a0.w);
    *(ull*)&Asd[0][lc+0][af1] = dup2(a1.x);
    *(ull*)&Asd[0][lc+1][af1] = dup2(a1.y);
    *(ull*)&Asd[0][lc+2][af1] = dup2(a1.z);
    *(ull*)&Asd[0][lc+3][af1] = dup2(a1.w);
    Wt[0][lc+0][wf0] = w0.x; Wt[0][lc+1][wf0] = w0.y; Wt[0][lc+2][wf0] = w0.z; Wt[0][lc+3][wf0] = w0.w;
    Wt[0][lc+0][wf1] = w1.x; Wt[0][lc+1][wf1] = w1.y; Wt[0][lc+2][wf1] = w1.z; Wt[0][lc+3][wf1] = w1.w;
    __syncthreads();

    const int nT = C_ >> 4;
    for (int it = 0; it < nT; it++) {
        int cur = it & 1;
        if (it + 1 < nT) {
            int k0 = (it + 1) << 4;
            a0 = *(const float4*)&A[(size_t)(m0 + lr)      * C_ + k0 + lc];
            a1 = *(const float4*)&A[(size_t)(m0 + lr + 64) * C_ + k0 + lc];
            w0 = *(const float4*)&A[(size_t)(n0 + lr)      * C_ + k0 + lc];
            w1 = *(const float4*)&A[(size_t)(n0 + lr + 64) * C_ + k0 + lc];
        }
        #pragma unroll
        for (int kk = 0; kk < 16; kk++) {
            ulonglong2 A0 = *(const ulonglong2*)&Asd[cur][kk][qa0];
            ulonglong2 A1 = *(const ulonglong2*)&Asd[cur][kk][qa1];
            ulonglong2 A2 = *(const ulonglong2*)&Asd[cur][kk][qa2];
            ulonglong2 A3 = *(const ulonglong2*)&Asd[cur][kk][qa3];
            ull ap[8] = { A0.x, A0.y, A1.x, A1.y, A2.x, A2.y, A3.x, A3.y };
            ulonglong2 W0 = *(const ulonglong2*)&Wt[cur][kk][qw0];
            ulonglong2 W1 = *(const ulonglong2*)&Wt[cur][kk][qw1];
            ull wp[4] = { W0.x, W0.y, W1.x, W1.y };
            #pragma unroll
            for (int i = 0; i < 8; i++)
                #pragma unroll
                for (int j = 0; j < 4; j++)
                    fma2(acc[i][j], ap[i], wp[j]);
        }
        if (it + 1 < nT) {
            int nb = cur ^ 1;
            __syncthreads();
            *(ull*)&Asd[nb][lc+0][af0] = dup2(a0.x);
            *(ull*)&Asd[nb][lc+1][af0] = dup2(a0.y);
            *(ull*)&Asd[nb][lc+2][af0] = dup2(a0.z);
            *(ull*)&Asd[nb][lc+3][af0] = dup2(a0.w);
            *(ull*)&Asd[nb][lc+0][af1] = dup2(a1.x);
            *(ull*)&Asd[nb][lc+1][af1] = dup2(a1.y);
            *(ull*)&Asd[nb][lc+2][af1] = dup2(a1.z);
            *(ull*)&Asd[nb][lc+3][af1] = dup2(a1.w);
            Wt[nb][lc+0][wf0] = w0.x; Wt[nb][lc+1][wf0] = w0.y;
            Wt[nb][lc+2][wf0] = w0.z; Wt[nb][lc+3][wf0] = w0.w;
            Wt[nb][lc+0][wf1] = w1.x; Wt[nb][lc+1][wf1] = w1.y;
            Wt[nb][lc+2][wf1] = w1.z; Wt[nb][lc+3][wf1] = w1.w;
            __syncthreads();
        }
    }

    float f[8][8];
    #pragma unroll
    for (int i = 0; i < 8; i++)
        #pragma unroll
        for (int j = 0; j < 4; j++) {
            float2 p = unpk(acc[i][j]);
            f[i][2*j] = p.x; f[i][2*j+1] = p.y;
        }

    float sn[8], sm[8];
    *(float4*)(sn)     = *(const float4*)&sb[n0 + tx*8];
    *(float4*)(sn + 4) = *(const float4*)&sb[n0 + tx*8 + 4];
    *(float4*)(sm)     = *(const float4*)&sb[m0 + ty*8];
    *(float4*)(sm + 4) = *(const float4*)&sb[m0 + ty*8 + 4];

    #pragma unroll
    for (int i = 0; i < 8; i++) {
        float o[8];
        #pragma unroll
        for (int j = 0; j < 8; j++) o[j] = sm[i] + sn[j] - 2.f * f[i][j];
        size_t r = (size_t)(m0 + ty*8 + i) * NPTS + n0 + tx*8;
        *(float4*)&D[r]     = *(float4*)(o);
        *(float4*)&D[r + 4] = *(float4*)(o + 4);
    }
    if (bi != bj) {
        #pragma unroll
        for (int j = 0; j < 8; j++) {
            float o[8];
            #pragma unroll
            for (int i = 0; i < 8; i++) o[i] = sn[j] + sm[i] - 2.f * f[i][j];
            size_t r = (size_t)(n0 + tx*8 + j) * NPTS + m0 + ty*8;
            *(float4*)&D[r]     = *(float4*)(o);
            *(float4*)&D[r + 4] = *(float4*)(o + 4);
        }
    }
}

// ---------------- BN apply q/k/v + fused sq ----------------
__global__ __launch_bounds__(256)
void bnqkv_kernel(const float* __restrict__ Y, float* __restrict__ out,
                  const float* __restrict__ gq, const float* __restrict__ bq,
                  const float* __restrict__ gk, const float* __restrict__ bk,
                  const float* __restrict__ gv, const float* __restrict__ bv,
                  float* __restrict__ sqv)
{
    int blk = blockIdx.x;
    int slice = blk >> 12;
    int row   = blk & 4095;
    int d = threadIdx.x;
    const float* gamma = slice == 0 ? gq : slice == 1 ? gk : gv;
    const float* beta  = slice == 0 ? bq : slice == 1 ? bk : bv;
    float a, c;
    foldco(slice, d, INV_M1, gamma, beta, a, c);
    size_t e = (size_t)blk * 256 + d;
    float z = a * Y[e] + c;
    float o = lrelu(z);
    out[e] = o;

    if (slice == 1) {
        __shared__ float sh[8];
        float s = o * o;
        #pragma unroll
        for (int off = 16; off; off >>= 1) s += __shfl_down_sync(0xffffffffu, s, off);
        if ((d & 31) == 0) sh[d >> 5] = s;
        __syncthreads();
        if (d == 0) {
            float t = 0.f;
            #pragma unroll
            for (int w = 0; w < 8; w++) t += sh[w];
            sqv[row] = t;
        }
    }
}

// ---------------- top-32 ----------------
#define CE(i,j) { if (vr[j] < vr[i] || (vr[j] == vr[i] && idr[j] < idr[i])) { \
                    float tv = vr[i]; vr[i] = vr[j]; vr[j] = tv; \
                    int ti = idr[i]; idr[i] = idr[j]; idr[j] = ti; } }

__global__ __launch_bounds__(256)
void topk_kernel(const float* __restrict__ dist)
{
    int bn = blockIdx.x;
    const float* row = dist + (size_t)bn * NPTS;
    int t = threadIdx.x;
    int lane = t & 31, wrp = t >> 5;

    __shared__ float lv[8][32];
    __shared__ int   li[8][32];

    {
        float vr[8]; int idr[8];
        #pragma unroll
        for (int s = 0; s < 8; s++) {
            int j = wrp * 256 + s * 32 + lane;
            vr[s] = row[j]; idr[s] = j;
        }
        CE(0,1) CE(2,3) CE(4,5) CE(6,7)
        CE(0,2) CE(1,3) CE(4,6) CE(5,7)
        CE(1,2) CE(5,6)
        CE(0,4) CE(1,5) CE(2,6) CE(3,7)
        CE(2,4) CE(3,5)
        CE(1,2) CE(3,4) CE(5,6)

        float outv = FLT_MAX; int outi = 0x7fffffff;
        for (int sel = 0; sel < KNB; sel++) {
            float cv = vr[0]; int ci = idr[0];
            int myhead = idr[0];
            #pragma unroll
            for (int o = 16; o; o >>= 1) {
                float ov = __shfl_xor_sync(0xffffffffu, cv, o);
                int   oi = __shfl_xor_sync(0xffffffffu, ci, o);
                if (ov < cv || (ov == cv && oi < ci)) { cv = ov; ci = oi; }
            }
            if (lane == sel) { outv = cv; outi = ci; }
            if (myhead == ci) {
                #pragma unroll
                for (int s = 0; s < 7; s++) { vr[s] = vr[s+1]; idr[s] = idr[s+1]; }
                vr[7] = FLT_MAX; idr[7] = 0x7fffffff;
            }
        }
        lv[wrp][lane] = outv;
        li[wrp][lane] = outi;
    }
    __syncthreads();

    if (wrp == 0) {
        float vr[8]; int idr[8];
        #pragma unroll
        for (int j = 0; j < 8; j++) { vr[j] = lv[j][lane]; idr[j] = li[j][lane]; }
        CE(0,1) CE(2,3) CE(4,5) CE(6,7)
        CE(0,2) CE(1,3) CE(4,6) CE(5,7)
        CE(1,2) CE(5,6)
        CE(0,4) CE(1,5) CE(2,6) CE(3,7)
        CE(2,4) CE(3,5)
        CE(1,2) CE(3,4) CE(5,6)

        for (int sel = 0; sel < KNB; sel++) {
            float cv = vr[0]; int ci = idr[0];
            int myhead = idr[0];
            #pragma unroll
            for (int o = 16; o; o >>= 1) {
                float ov = __shfl_xor_sync(0xffffffffu, cv, o);
                int   oi = __shfl_xor_sync(0xffffffffu, ci, o);
                if (ov < cv || (ov == cv && oi < ci)) { cv = ov; ci = oi; }
            }
            if (lane == 0) g_idx[(size_t)bn * KNB + sel] = ci;
            if (myhead == ci) {
                #pragma unroll
                for (int s = 0; s < 7; s++) { vr[s] = vr[s+1]; idr[s] = idr[s+1]; }
                vr[7] = FLT_MAX; idr[7] = 0x7fffffff;
            }
        }
    }
}

// ---------------- stats infra ----------------
__global__ void zero_all_stats()
{
    int i = blockIdx.x * 256 + threadIdx.x;
    if (i < 8 * HID) { ((double*)g_dsum)[i] = 0.0; ((double*)g_dsum2)[i] = 0.0; }
}

// ---------------- posb stats via moments ----------------
__global__ __launch_bounds__(256)
void pbstats_kernel(const float* __restrict__ P)
{
    int d = threadIdx.x;
    float s = 0.f, s2 = 0.f;
    for (int gidx = 0; gidx < 16; gidx++) {
        int bn = blockIdx.x * 16 + gidx;
        int b  = bn >> 11;
        float pn = P[(size_t)bn * C_ + d];
        const int* ip = &g_idx[(size_t)bn * KNB];
        float A1 = 0.f, A2 = 0.f;
        #pragma unroll 4
        for (int k = 0; k < KNB; k++) {
            int jg = (b << 11) + ip[k];
            float v = P[(size_t)jg * C_ + d];
            A1 += v; A2 += v * v;
        }
        s  += A1 - 32.f * pn;
        s2 += A2 - 2.f * pn * A1 + 32.f * pn * pn;
    }
    atomicAdd(&g_dsum[ST_PB][d],  (double)s);
    atomicAdd(&g_dsum2[ST_PB][d], (double)s2);
}

// ---------------- final BN+silu+residual ----------------
__global__ void bn_silu_res_apply(const float* __restrict__ Y, const float* __restrict__ res,
                                  float* __restrict__ out,
                                  const float* __restrict__ gm2, const float* __restrict__ bm2)
{
    int d = threadIdx.x;
    float a, c;
    foldco(ST_M2, d, INV_M1, gm2, bm2, a, c);
    size_t e = (size_t)blockIdx.x * 256 + d;
    float z = a * Y[e] + c;
    out[e] = res[e] + z / (1.f + expf(-z));
}

// ---------------- vec1: PIPELINED gather GEMM (double-barrier schedule) ----------------
__global__ __launch_bounds__(256)
void vec1_kernel(const float* __restrict__ qb, const float* __restrict__ kb,
                 const float* __restrict__ P,  const float* __restrict__ We1,
                 const float* __restrict__ gpb, const float* __restrict__ bpb,
                 float* __restrict__ s1)
{
    __shared__ __align__(16) float As[2][16][128];
    __shared__ __align__(16) float Wsd[2][16][64];
    __shared__ __align__(16) float spa[C_], spc[C_];
    __shared__ int sj[128];
    __shared__ float cs[8][32], cs2[8][32];
    int tid = threadIdx.x;
    int m0 = blockIdx.x * 128;
    foldco(ST_PB, tid, INV_M2, gpb, bpb, spa[tid], spc[tid]);
    if (tid < 128) sj[tid] = g_idx[m0 + tid];
    __syncthreads();

    int tx = tid & 15, ty = tid >> 4;
    int lr = tid >> 2;
    int lc = (tid & 3) << 2;
    int r0 = m0 + lr,      bn0 = r0 >> 5, b0 = r0 >> 16;
    int r1 = m0 + lr + 64, bn1 = r1 >> 5, b1 = r1 >> 16;
    int jg0 = (b0 << 11) + sj[lr];
    int jg1 = (b1 << 11) + sj[lr + 64];
    ull acc[4][2] = {};

    float4 kf0, qf0, pj0, pn0, kf1, qf1, pj1, pn1;
    float ws0, ws1;

#define V_LOAD(K0) { \
        kf0 = *(const float4*)&kb[(size_t)jg0 * C_ + (K0) + lc]; \
        qf0 = *(const float4*)&qb[(size_t)bn0 * C_ + (K0) + lc]; \
        pj0 = *(const float4*)&P [(size_t)jg0 * C_ + (K0) + lc]; \
        pn0 = *(const float4*)&P [(size_t)bn0 * C_ + (K0) + lc]; \
        kf1 = *(const float4*)&kb[(size_t)jg1 * C_ + (K0) + lc]; \
        qf1 = *(const float4*)&qb[(size_t)bn1 * C_ + (K0) + lc]; \
        pj1 = *(const float4*)&P [(size_t)jg1 * C_ + (K0) + lc]; \
        pn1 = *(const float4*)&P [(size_t)bn1 * C_ + (K0) + lc]; \
        ws0 = We1[(size_t)(tid & 31) * C_ + (K0) + (tid >> 5)]; \
        ws1 = We1[(size_t)(tid & 31) * C_ + (K0) + (tid >> 5) + 8]; }
#define V_STS(BF, K0) { \
        float4 pa = *(const float4*)&spa[(K0) + lc]; \
        float4 pc = *(const float4*)&spc[(K0) + lc]; \
        As[BF][lc+0][lr] = kf0.x - qf0.x + lrelu(pa.x * (pj0.x - pn0.x) + pc.x); \
        As[BF][lc+1][lr] = kf0.y - qf0.y + lrelu(pa.y * (pj0.y - pn0.y) + pc.y); \
        As[BF][lc+2][lr] = kf0.z - qf0.z + lrelu(pa.z * (pj0.z - pn0.z) + pc.z); \
        As[BF][lc+3][lr] = kf0.w - qf0.w + lrelu(pa.w * (pj0.w - pn0.w) + pc.w); \
        As[BF][lc+0][lr+64] = kf1.x - qf1.x + lrelu(pa.x * (pj1.x - pn1.x) + pc.x); \
        As[BF][lc+1][lr+64] = kf1.y - qf1.y + lrelu(pa.y * (pj1.y - pn1.y) + pc.y); \
        As[BF][lc+2][lr+64] = kf1.z - qf1.z + lrelu(pa.z * (pj1.z - pn1.z) + pc.z); \
        As[BF][lc+3][lr+64] = kf1.w - qf1.w + lrelu(pa.w * (pj1.w - pn1.w) + pc.w); \
        *(ull*)&Wsd[BF][tid >> 5][2*(tid & 31)]       = dup2(ws0); \
        *(ull*)&Wsd[BF][(tid >> 5) + 8][2*(tid & 31)] = dup2(ws1); }

    V_LOAD(0)
    V_STS(0, 0)
    __syncthreads();
    const int nT = C_ >> 4;
    for (int it = 0; it < nT; it++) {
        int cur = it & 1;
        if (it + 1 < nT) V_LOAD((it + 1) << 4)
        #pragma unroll
        for (int kk = 0; kk < 16; kk++) {
            ulonglong2 aA = *(const ulonglong2*)&As[cur][kk][ty*8];
            ulonglong2 aB = *(const ulonglong2*)&As[cur][kk][ty*8 + 4];
            ull ap[4] = { aA.x, aA.y, aB.x, aB.y };
            ulonglong2 wv = *(const ulonglong2*)&Wsd[cur][kk][4*tx];
            #pragma unroll
            for (int i2 = 0; i2 < 4; i2++) {
                fma2(acc[i2][0], ap[i2], wv.x);
                fma2(acc[i2][1], ap[i2], wv.y);
            }
        }
        if (it + 1 < nT) {
            __syncthreads();               // all compute on next buffer done
            V_STS(cur ^ 1, (it + 1) << 4)
            __syncthreads();
        }
    }
#undef V_LOAD
#undef V_STS

    #pragma unroll
    for (int i2 = 0; i2 < 4; i2++) {
        float2 p0 = unpk(acc[i2][0]), p1 = unpk(acc[i2][1]);
        size_t w0 = (size_t)(m0 + ty*8 + 2*i2) * CPH + tx*2;
        s1[w0]           = p0.x; s1[w0 + 1]       = p1.x;
        s1[w0 + CPH]     = p0.y; s1[w0 + CPH + 1] = p1.y;
    }
    float ps[2], ps2[2];
    #pragma unroll
    for (int j = 0; j < 2; j++) {
        ull s = add2(add2(acc[0][j], acc[1][j]), add2(acc[2][j], acc[3][j]));
        ull q = add2(add2(mul2(acc[0][j], acc[0][j]), mul2(acc[1][j], acc[1][j])),
                     add2(mul2(acc[2][j], acc[2][j]), mul2(acc[3][j], acc[3][j])));
        float2 fs = unpk(s), fq = unpk(q);
        ps[j] = fs.x + fs.y; ps2[j] = fq.x + fq.y;
    }
    ps[0]  += __shfl_down_sync(0xffffffffu, ps[0], 16);
    ps[1]  += __shfl_down_sync(0xffffffffu, ps[1], 16);
    ps2[0] += __shfl_down_sync(0xffffffffu, ps2[0], 16);
    ps2[1] += __shfl_down_sync(0xffffffffu, ps2[1], 16);
    int lane = tid & 31, wrp = tid >> 5;
    if (lane < 16) {
        cs[wrp][tx*2]      = ps[0];  cs[wrp][tx*2 + 1]  = ps[1];
        cs2[wrp][tx*2]     = ps2[0]; cs2[wrp][tx*2 + 1] = ps2[1];
    }
    __syncthreads();
    if (tid < 32) {
        double s = 0.0, s2 = 0.0;
        #pragma unroll
        for (int w = 0; w < 8; w++) { s += cs[w][tid]; s2 += cs2[w][tid]; }
        atomicAdd(&g_dsum[ST_S1][tid], s);
        atomicAdd(&g_dsum2[ST_S1][tid], s2);
    }
}

// ---------------- vec2 (R12 version) ----------------
__global__ __launch_bounds__(256)
void vec2_kernel(const float* __restrict__ s1, const float* __restrict__ We2,
                 const float* __restrict__ ge1, const float* __restrict__ be1,
                 float* __restrict__ s2)
{
    __shared__ __align__(16) float As[16][128];
    __shared__ __align__(16) float Wsd[16][64];
    __shared__ __align__(16) float sfa[CPH], sfc[CPH];
    __shared__ float cs[8][32], cs2[8][32];
    int tid = threadIdx.x;
    int m0 = blockIdx.x * 128;
    if (tid < CPH) foldco(ST_S1, tid, INV_M2, ge1, be1, sfa[tid], sfc[tid]);
    __syncthreads();

    int tx = tid & 15, ty = tid >> 4;
    int lr = tid >> 2;
    int lc = (tid & 3) << 2;
    ull acc[4][2] = {};

    for (int k0 = 0; k0 < CPH; k0 += 16) {
        #pragma unroll
        for (int h = 0; h < 2; h++) {
            int rr = h ? lr + 64 : lr;
            float4 y  = *(const float4*)&s1[(size_t)(m0 + rr) * CPH + k0 + lc];
            float4 aa = *(const float4*)&sfa[k0 + lc];
            float4 cc = *(const float4*)&sfc[k0 + lc];
            As[lc+0][rr] = lrelu(aa.x * y.x + cc.x);
            As[lc+1][rr] = lrelu(aa.y * y.y + cc.y);
            As[lc+2][rr] = lrelu(aa.z * y.z + cc.z);
            As[lc+3][rr] = lrelu(aa.w * y.w + cc.w);
        }
        {
            int i0 = tid;
            *(ull*)&Wsd[i0 >> 5][2*(i0 & 31)] = dup2(We2[(size_t)(i0 & 31) * CPH + k0 + (i0 >> 5)]);
            int i1 = tid + 256;
            *(ull*)&Wsd[i1 >> 5][2*(i1 & 31)] = dup2(We2[(size_t)(i1 & 31) * CPH + k0 + (i1 >> 5)]);
        }
        __syncthreads();
        #pragma unroll
        for (int kk = 0; kk < 16; kk++) {
            ulonglong2 aA = *(const ulonglong2*)&As[kk][ty*8];
            ulonglong2 aB = *(const ulonglong2*)&As[kk][ty*8 + 4];
            ull ap[4] = { aA.x, aA.y, aB.x, aB.y };
            ulonglong2 wv = *(const ulonglong2*)&Wsd[kk][4*tx];
            #pragma unroll
            for (int i2 = 0; i2 < 4; i2++) {
                fma2(acc[i2][0], ap[i2], wv.x);
                fma2(acc[i2][1], ap[i2], wv.y);
            }
        }
        __syncthreads();
    }
    #pragma unroll
    for (int i2 = 0; i2 < 4; i2++) {
        float2 p0 = unpk(acc[i2][0]), p1 = unpk(acc[i2][1]);
        size_t w0 = (size_t)(m0 + ty*8 + 2*i2) * CPH + tx*2;
        s2[w0]           = p0.x; s2[w0 + 1]       = p1.x;
        s2[w0 + CPH]     = p0.y; s2[w0 + CPH + 1] = p1.y;
    }
    float ps[2], ps2[2];
    #pragma unroll
    for (int j = 0; j < 2; j++) {
        ull s = add2(add2(acc[0][j], acc[1][j]), add2(acc[2][j], acc[3][j]));
        ull q = add2(add2(mul2(acc[0][j], acc[0][j]), mul2(acc[1][j], acc[1][j])),
                     add2(mul2(acc[2][j], acc[2][j]), mul2(acc[3][j], acc[3][j])));
        float2 fs = unpk(s), fq = unpk(q);
        ps[j] = fs.x + fs.y; ps2[j] = fq.x + fq.y;
    }
    ps[0]  += __shfl_down_sync(0xffffffffu, ps[0], 16);
    ps[1]  += __shfl_down_sync(0xffffffffu, ps[1], 16);
    ps2[0] += __shfl_down_sync(0xffffffffu, ps2[0], 16);
    ps2[1] += __shfl_down_sync(0xffffffffu, ps2[1], 16);
    int lane = tid & 31, wrp = tid >> 5;
    if (lane < 16) {
        cs[wrp][tx*2]      = ps[0];  cs[wrp][tx*2 + 1]  = ps[1];
        cs2[wrp][tx*2]     = ps2[0]; cs2[wrp][tx*2 + 1] = ps2[1];
    }
    __syncthreads();
    if (tid < 32) {
        double s = 0.0, s2 = 0.0;
        #pragma unroll
        for (int w = 0; w < 8; w++) { s += cs[w][tid]; s2 += cs2[w][tid]; }
        atomicAdd(&g_dsum[ST_S2][tid], s);
        atomicAdd(&g_dsum2[ST_S2][tid], s2);
    }
}

// ---------------- attention ----------------
__global__ __launch_bounds__(256)
void attn_kernel(const float* __restrict__ x, const float* __restrict__ s2,
                 const float* __restrict__ vb, const float* __restrict__ P,
                 const float* __restrict__ ge2, const float* __restrict__ be2,
                 const float* __restrict__ gpb, const float* __restrict__ bpb,
                 float* __restrict__ xattn)
{
    int bn = blockIdx.x;
    int t = threadIdx.x;
    __shared__ float soft[KNB][CPH + 1];
    __shared__ float ssa[CPH], ssc[CPH];
    __shared__ int sj[KNB];
    if (t < CPH) foldco(ST_S2, t, INV_M2, ge2, be2, ssa[t], ssc[t]);
    if (t >= 32 && t < 64) sj[t - 32] = g_idx[(size_t)bn * KNB + t - 32];
    float pa, pc;
    foldco(ST_PB, t, INV_M2, gpb, bpb, pa, pc);
    __syncthreads();

    size_t base = (size_t)bn * KNB * CPH;
    for (int e = t; e < KNB * CPH; e += 256) {
        int g = e & 31;
        float y = s2[base + e];
        soft[e >> 5][g] = lrelu(ssa[g] * y + ssc[g]);
    }
    __syncthreads();
    if (t < CPH) {
        float mx = -FLT_MAX;
        #pragma unroll
        for (int k = 0; k < KNB; k++) mx = fmaxf(mx, soft[k][t]);
        float s = 0.f;
        #pragma unroll
        for (int k = 0; k < KNB; k++) { float ev = expf(soft[k][t] - mx); soft[k][t] = ev; s += ev; }
        float inv = 1.f / s;
        #pragma unroll
        for (int k = 0; k < KNB; k++) soft[k][t] *= inv;
    }
    __syncthreads();

    int c = t, g = t >> 3;
    int b = bn >> 11;
    float pn = P[(size_t)bn * C_ + c];
    float acc = 0.f;
    #pragma unroll
    for (int k = 0; k < KNB; k++) {
        int jg = (b << 11) + sj[k];
        float posb = lrelu(pa * (P[(size_t)jg * C_ + c] - pn) + pc);
        acc += (vb[(size_t)jg * C_ + c] + posb) * soft[k][g];
    }
    size_t o = (size_t)bn * C_ + c;
    xattn[o] = x[o] + acc;
}

extern "C" void kernel_launch(void* const* d_in, const int* in_sizes, int n_in,
                              void* d_out, int out_size)
{
    const float* x   = (const float*)d_in[0];
    const float* pos = (const float*)d_in[1];
    const float* Wq  = (const float*)d_in[2];
    const float* gq  = (const float*)d_in[3];
    const float* bq  = (const float*)d_in[4];
    const float* Wk  = (const float*)d_in[5];
    const float* gk  = (const float*)d_in[6];
    const float* bk  = (const float*)d_in[7];
    const float* Wv  = (const float*)d_in[8];
    const float* gv  = (const float*)d_in[9];
    const float* bv  = (const float*)d_in[10];
    const float* Wpb = (const float*)d_in[11];
    const float* gpb = (const float*)d_in[12];
    const float* bpb = (const float*)d_in[13];
    const float* We1 = (const float*)d_in[14];
    const float* ge1 = (const float*)d_in[15];
    const float* be1 = (const float*)d_in[16];
    const float* We2 = (const float*)d_in[17];
    const float* ge2 = (const float*)d_in[18];
    const float* be2 = (const float*)d_in[19];
    const float* Wm1 = (const float*)d_in[20];
    const float* gm1 = (const float*)d_in[21];
    const float* bm1 = (const float*)d_in[22];
    const float* Wm2 = (const float*)d_in[23];
    const float* gm2 = (const float*)d_in[24];
    const float* bm2 = (const float*)d_in[25];
    float* out = (float*)d_out;

    void* p;
    float *qkv, *tmp, *sqv, *dist, *s1, *s2, *xatt;
    cudaGetSymbolAddress(&p, g_qkv);   qkv  = (float*)p;
    cudaGetSymbolAddress(&p, g_tmp4);  tmp  = (float*)p;
    cudaGetSymbolAddress(&p, g_sqv);   sqv  = (float*)p;
    cudaGetSymbolAddress(&p, g_dist);  dist = (float*)p;
    cudaGetSymbolAddress(&p, g_s1);    s1   = (float*)p;
    cudaGetSymbolAddress(&p, g_s2);    s2   = (float*)p;
    cudaGetSymbolAddress(&p, g_xattn); xatt = (float*)p;

    const size_t SL = (size_t)M1 * C_;
    float* t0 = tmp;
    float* t1 = tmp + SL;
    float* t2 = tmp + 2*SL;
    float* t3 = tmp + 3*SL;
    float* qb = qkv;
    float* kb = qkv + SL;
    float* vb = qkv + 2*SL;

    zero_all_stats<<<16, 256>>>();
    {
        Gemm4 g = { { x, x, x, pos }, { Wq, Wk, Wv, Wpb }, { t0, t1, t2, t3 },
                    { ST_Q, ST_K, ST_V, -1 } };
        gemm128p_kernel<<<dim3(C_/128, M1/128, 4), 256>>>(g, C_, C_);
    }
    bnqkv_kernel<<<3 * M1, 256>>>(tmp, qkv, gq, bq, gk, bk, gv, bv, sqv);
    dist_kernel<<<dim3(136, 1, B_), 256>>>(kb, sqv, dist);
    topk_kernel<<<M1, 256>>>(dist);
    pbstats_kernel<<<256, 256>>>(t3);
    vec1_kernel<<<M2/128, 256>>>(qb, kb, t3, We1, gpb, bpb, s1);
    vec2_kernel<<<M2/128, 256>>>(s1, We2, ge1, be1, s2);
    attn_kernel<<<M1, 256>>>(x, s2, vb, t3, ge2, be2, gpb, bpb, xatt);
    {
        Gemm4 g = { { xatt, 0, 0, 0 }, { Wm1, 0, 0, 0 }, { t0, 0, 0, 0 },
                    { ST_M1, -1, -1, -1 } };
        gemm128p_kernel<<<dim3(HID/128, M1/128, 1), 256>>>(g, HID, C_);
    }
    {
        Gemm4 g = { { t0, 0, 0, 0 }, { Wm2, 0, 0, 0 }, { t2, 0, 0, 0 },
                    { ST_M2, -1, -1, -1 } };
        gemm128_kernel<<<dim3(C_/128, M1/128, 1), 256>>>(g, C_, HID, 1, gm1, bm1);
    }
    bn_silu_res_apply<<<M1, 256>>>(t2, xatt, out, gm2, bm2);
}

// round 14
// speedup vs baseline: 1.0996x; 1.0560x over previous
#include <cuda_runtime.h>
#include <math.h>
#include <float.h>

#define B_   2
#define NPTS 2048
#define C_   256
#define KNB  32
#define HID  512
#define CPH  32
#define M1   (B_*NPTS)        // 4096
#define M2   (B_*NPTS*KNB)    // 131072
#define EPSB 1e-5f

#define ST_Q  0
#define ST_K  1
#define ST_V  2
#define ST_PB 3
#define ST_S1 4
#define ST_S2 5
#define ST_M1 6
#define ST_M2 7

#define INV_M1 (1.0/4096.0)
#define INV_M2 (1.0/131072.0)

typedef unsigned long long ull;

// ---------------- device scratch ----------------
__device__ float g_qkv[3*M1*C_];
__device__ float g_tmp4[(size_t)M1*C_*4];
__device__ float g_sqv[M1];
__device__ float g_dist[(size_t)B_*NPTS*NPTS];
__device__ int   g_idx[M2];
__device__ float g_s1[(size_t)M2*CPH];
__device__ float g_s2[(size_t)M2*CPH];
__device__ float g_xattn[M1*C_];
__device__ double g_dsum[8][HID];
__device__ double g_dsum2[8][HID];

__device__ __forceinline__ float lrelu(float z) { return z >= 0.f ? z : 0.2f * z; }

__device__ __forceinline__ void foldco(int stage, int d, double invM,
                                       const float* __restrict__ gamma,
                                       const float* __restrict__ beta,
                                       float& a, float& c)
{
    double m = g_dsum[stage][d] * invM;
    double v = g_dsum2[stage][d] * invM - m * m;
    if (v < 0.0) v = 0.0;
    a = gamma[d] * rsqrtf((float)v + EPSB);
    c = beta[d] - (float)m * a;
}

// ---------------- packed f32x2 helpers ----------------
__device__ __forceinline__ void fma2(ull& d, ull a, ull b) {
    asm("fma.rn.f32x2 %0, %1, %2, %0;" : "+l"(d) : "l"(a), "l"(b));
}
__device__ __forceinline__ ull add2(ull a, ull b) {
    ull d; asm("add.rn.f32x2 %0, %1, %2;" : "=l"(d) : "l"(a), "l"(b)); return d;
}
__device__ __forceinline__ ull mul2(ull a, ull b) {
    ull d; asm("mul.rn.f32x2 %0, %1, %2;" : "=l"(d) : "l"(a), "l"(b)); return d;
}
__device__ __forceinline__ ull dup2(float x) {
    ull r; asm("mov.b64 %0, {%1, %1};" : "=l"(r) : "f"(x)); return r;
}
__device__ __forceinline__ float2 unpk(ull v) {
    float2 f; asm("mov.b64 {%0, %1}, %2;" : "=f"(f.x), "=f"(f.y) : "l"(v)); return f;
}

// quad XOR swizzle for 32-quad rows (128 floats)
__device__ __forceinline__ int q32(int p) { return p ^ (p >> 3); }

struct Gemm4 {
    const float* A[4];
    const float* W[4];
    float*       C[4];
    int          stage[4];
};

// common per-kk compute: A read as 2 float4 (broadcast), dup in regs; W pair-reads
#define MAIN_FMA(ASQ, WTQ) { \
        float4 Af0 = *(const float4*)&ASQ[kk][ra0]; \
        float4 Af1 = *(const float4*)&ASQ[kk][ra1]; \
        ull ap[8] = { dup2(Af0.x), dup2(Af0.y), dup2(Af0.z), dup2(Af0.w), \
                      dup2(Af1.x), dup2(Af1.y), dup2(Af1.z), dup2(Af1.w) }; \
        ulonglong2 W0 = *(const ulonglong2*)&WTQ[kk][qw0]; \
        ulonglong2 W1 = *(const ulonglong2*)&WTQ[kk][qw1]; \
        ull wp[4] = { W0.x, W0.y, W1.x, W1.y }; \
        _Pragma("unroll") \
        for (int i = 0; i < 8; i++) \
            _Pragma("unroll") \
            for (int j = 0; j < 4; j++) \
                fma2(acc[i][j], ap[i], wp[j]); }

// ================= PIPELINED FMA2 GEMM, A un-duplicated =================
__global__ __launch_bounds__(256, 2)
void gemm128p_kernel(Gemm4 g, int N, int K)
{
    __shared__ __align__(16) float Asq[2][16][128];   // 16 KB
    __shared__ __align__(16) float Wt[2][16][128];    // 16 KB
    int z = blockIdx.z;
    const float* A = g.A[z];
    const float* W = g.W[z];
    float*       C = g.C[z];
    int stage = g.stage[z];
    int tid = threadIdx.x;

    int tx = tid & 15, ty = tid >> 4;
    int m0 = blockIdx.y * 128, n0 = blockIdx.x * 128;
    int lr = tid >> 2;
    int lc = (tid & 3) << 2;

    int wf0 = (q32(lr >> 2) << 2) | (lr & 3);
    int wf1 = (q32((lr + 64) >> 2) << 2) | (lr & 3);
    int ra0 = q32(2 * ty) << 2;
    int ra1 = q32(2 * ty + 1) << 2;
    int qw0 = q32(2 * tx) << 2;
    int qw1 = q32(2 * tx + 1) << 2;

    ull acc[8][4] = {};
    float4 a0, a1, w0, w1;

#define P_STS(BF) { \
        Asq[BF][lc+0][wf0] = a0.x; Asq[BF][lc+1][wf0] = a0.y; \
        Asq[BF][lc+2][wf0] = a0.z; Asq[BF][lc+3][wf0] = a0.w; \
        Asq[BF][lc+0][wf1] = a1.x; Asq[BF][lc+1][wf1] = a1.y; \
        Asq[BF][lc+2][wf1] = a1.z; Asq[BF][lc+3][wf1] = a1.w; \
        Wt[BF][lc+0][wf0] = w0.x; Wt[BF][lc+1][wf0] = w0.y; \
        Wt[BF][lc+2][wf0] = w0.z; Wt[BF][lc+3][wf0] = w0.w; \
        Wt[BF][lc+0][wf1] = w1.x; Wt[BF][lc+1][wf1] = w1.y; \
        Wt[BF][lc+2][wf1] = w1.z; Wt[BF][lc+3][wf1] = w1.w; }

    a0 = *(const float4*)&A[(size_t)(m0 + lr)      * K + lc];
    a1 = *(const float4*)&A[(size_t)(m0 + lr + 64) * K + lc];
    w0 = *(const float4*)&W[(size_t)(n0 + lr)      * K + lc];
    w1 = *(const float4*)&W[(size_t)(n0 + lr + 64) * K + lc];
    P_STS(0)
    __syncthreads();

    const int nT = K >> 4;
    for (int it = 0; it < nT; it++) {
        int cur = it & 1;
        if (it + 1 < nT) {
            int k0 = (it + 1) << 4;
            a0 = *(const float4*)&A[(size_t)(m0 + lr)      * K + k0 + lc];
            a1 = *(const float4*)&A[(size_t)(m0 + lr + 64) * K + k0 + lc];
            w0 = *(const float4*)&W[(size_t)(n0 + lr)      * K + k0 + lc];
            w1 = *(const float4*)&W[(size_t)(n0 + lr + 64) * K + k0 + lc];
        }
        #pragma unroll
        for (int kk = 0; kk < 16; kk++) MAIN_FMA(Asq[cur], Wt[cur])
        if (it + 1 < nT) {
            int nb = cur ^ 1;
            __syncthreads();
            { int BF = nb; P_STS(BF) }
            __syncthreads();
        }
    }
#undef P_STS

    #pragma unroll
    for (int i = 0; i < 8; i++) {
        float o[8];
        #pragma unroll
        for (int j = 0; j < 4; j++) {
            float2 p = unpk(acc[i][j]);
            o[2*j] = p.x; o[2*j+1] = p.y;
        }
        size_t r = (size_t)(m0 + ty*8 + i) * N + n0 + tx*8;
        *(float4*)&C[r]     = *(float4*)(o);
        *(float4*)&C[r + 4] = *(float4*)(o + 4);
    }

    if (stage >= 0) {
        float ps[8], ps2[8];
        #pragma unroll
        for (int j = 0; j < 4; j++) {
            ull s = add2(add2(add2(acc[0][j], acc[1][j]), add2(acc[2][j], acc[3][j])),
                         add2(add2(acc[4][j], acc[5][j]), add2(acc[6][j], acc[7][j])));
            ull q = add2(add2(add2(mul2(acc[0][j],acc[0][j]), mul2(acc[1][j],acc[1][j])),
                              add2(mul2(acc[2][j],acc[2][j]), mul2(acc[3][j],acc[3][j]))),
                         add2(add2(mul2(acc[4][j],acc[4][j]), mul2(acc[5][j],acc[5][j])),
                              add2(mul2(acc[6][j],acc[6][j]), mul2(acc[7][j],acc[7][j]))));
            float2 fs = unpk(s), fq = unpk(q);
            ps[2*j] = fs.x; ps[2*j+1] = fs.y;
            ps2[2*j] = fq.x; ps2[2*j+1] = fq.y;
        }
        #pragma unroll
        for (int j = 0; j < 8; j++) {
            ps[j]  += __shfl_down_sync(0xffffffffu, ps[j], 16);
            ps2[j] += __shfl_down_sync(0xffffffffu, ps2[j], 16);
        }
        float (*red)[128] = (float(*)[128])&Asq[0][0][0];
        int lane = tid & 31, wrp = tid >> 5;
        __syncthreads();
        if (lane < 16) {
            #pragma unroll
            for (int j = 0; j < 8; j++) {
                red[wrp][tx*8 + j]     = ps[j];
                red[wrp + 8][tx*8 + j] = ps2[j];
            }
        }
        __syncthreads();
        if (tid < 128) {
            double s = 0.0, s2 = 0.0;
            #pragma unroll
            for (int w = 0; w < 8; w++) { s += red[w][tid]; s2 += red[w + 8][tid]; }
            atomicAdd(&g_dsum[stage][n0 + tid], s);
            atomicAdd(&g_dsum2[stage][n0 + tid], s2);
        }
    }
}

// ================= single-buffer gemm, dosilu fused, A un-duplicated (MLP2) =================
__global__ __launch_bounds__(256, 2)
void gemm128_kernel(Gemm4 g, int N, int K, int dosilu,
                    const float* __restrict__ fg, const float* __restrict__ fb)
{
    __shared__ __align__(16) float Asq[16][128];
    __shared__ __align__(16) float Wt[16][128];
    __shared__ float sfa[HID], sfc[HID];
    int z = blockIdx.z;
    const float* A = g.A[z];
    const float* W = g.W[z];
    float*       C = g.C[z];
    int stage = g.stage[z];
    int tid = threadIdx.x;

    if (dosilu) {
        for (int d = tid; d < K; d += 256)
            foldco(ST_M1, d, INV_M1, fg, fb, sfa[d], sfc[d]);
        __syncthreads();
    }

    int tx = tid & 15, ty = tid >> 4;
    int m0 = blockIdx.y * 128, n0 = blockIdx.x * 128;
    int lr = tid >> 2;
    int lc = (tid & 3) << 2;

    int wf0 = (q32(lr >> 2) << 2) | (lr & 3);
    int wf1 = (q32((lr + 64) >> 2) << 2) | (lr & 3);
    int ra0 = q32(2 * ty) << 2;
    int ra1 = q32(2 * ty + 1) << 2;
    int qw0 = q32(2 * tx) << 2;
    int qw1 = q32(2 * tx + 1) << 2;

    ull acc[8][4] = {};

    for (int k0 = 0; k0 < K; k0 += 16) {
        float4 a0 = *(const float4*)&A[(size_t)(m0 + lr)      * K + k0 + lc];
        float4 a1 = *(const float4*)&A[(size_t)(m0 + lr + 64) * K + k0 + lc];
        if (dosilu) {
            #pragma unroll
            for (int i = 0; i < 4; i++) {
                float aa = sfa[k0 + lc + i];
                float cc = sfc[k0 + lc + i];
                float* pz = (i==0)?&a0.x:(i==1)?&a0.y:(i==2)?&a0.z:&a0.w;
                float* pw = (i==0)?&a1.x:(i==1)?&a1.y:(i==2)?&a1.z:&a1.w;
                float z0 = aa * (*pz) + cc; *pz = z0 / (1.f + __expf(-z0));
                float z1 = aa * (*pw) + cc; *pw = z1 / (1.f + __expf(-z1));
            }
        }
        float4 w0 = *(const float4*)&W[(size_t)(n0 + lr)      * K + k0 + lc];
        float4 w1 = *(const float4*)&W[(size_t)(n0 + lr + 64) * K + k0 + lc];
        Asq[lc+0][wf0] = a0.x; Asq[lc+1][wf0] = a0.y; Asq[lc+2][wf0] = a0.z; Asq[lc+3][wf0] = a0.w;
        Asq[lc+0][wf1] = a1.x; Asq[lc+1][wf1] = a1.y; Asq[lc+2][wf1] = a1.z; Asq[lc+3][wf1] = a1.w;
        Wt[lc+0][wf0] = w0.x; Wt[lc+1][wf0] = w0.y; Wt[lc+2][wf0] = w0.z; Wt[lc+3][wf0] = w0.w;
        Wt[lc+0][wf1] = w1.x; Wt[lc+1][wf1] = w1.y; Wt[lc+2][wf1] = w1.z; Wt[lc+3][wf1] = w1.w;
        __syncthreads();
        #pragma unroll
        for (int kk = 0; kk < 16; kk++) MAIN_FMA(Asq, Wt)
        __syncthreads();
    }

    #pragma unroll
    for (int i = 0; i < 8; i++) {
        float o[8];
        #pragma unroll
        for (int j = 0; j < 4; j++) {
            float2 p = unpk(acc[i][j]);
            o[2*j] = p.x; o[2*j+1] = p.y;
        }
        size_t r = (size_t)(m0 + ty*8 + i) * N + n0 + tx*8;
        *(float4*)&C[r]     = *(float4*)(o);
        *(float4*)&C[r + 4] = *(float4*)(o + 4);
    }

    if (stage >= 0) {
        float ps[8], ps2[8];
        #pragma unroll
        for (int j = 0; j < 4; j++) {
            ull s = add2(add2(add2(acc[0][j], acc[1][j]), add2(acc[2][j], acc[3][j])),
                         add2(add2(acc[4][j], acc[5][j]), add2(acc[6][j], acc[7][j])));
            ull q = add2(add2(add2(mul2(acc[0][j],acc[0][j]), mul2(acc[1][j],acc[1][j])),
                              add2(mul2(acc[2][j],acc[2][j]), mul2(acc[3][j],acc[3][j]))),
                         add2(add2(mul2(acc[4][j],acc[4][j]), mul2(acc[5][j],acc[5][j])),
                              add2(mul2(acc[6][j],acc[6][j]), mul2(acc[7][j],acc[7][j]))));
            float2 fs = unpk(s), fq = unpk(q);
            ps[2*j] = fs.x; ps[2*j+1] = fs.y;
            ps2[2*j] = fq.x; ps2[2*j+1] = fq.y;
        }
        #pragma unroll
        for (int j = 0; j < 8; j++) {
            ps[j]  += __shfl_down_sync(0xffffffffu, ps[j], 16);
            ps2[j] += __shfl_down_sync(0xffffffffu, ps2[j], 16);
        }
        float (*red)[128] = (float(*)[128])&Asq[0][0];
        int lane = tid & 31, wrp = tid >> 5;
        __syncthreads();
        if (lane < 16) {
            #pragma unroll
            for (int j = 0; j < 8; j++) {
                red[wrp][tx*8 + j]     = ps[j];
                red[wrp + 8][tx*8 + j] = ps2[j];
            }
        }
        __syncthreads();
        if (tid < 128) {
            double s = 0.0, s2 = 0.0;
            #pragma unroll
            for (int w = 0; w < 8; w++) { s += red[w][tid]; s2 += red[w + 8][tid]; }
            atomicAdd(&g_dsum[stage][n0 + tid], s);
            atomicAdd(&g_dsum2[stage][n0 + tid], s2);
        }
    }
}

// ================= symmetric dist, pipelined, A un-duplicated =================
__global__ __launch_bounds__(256, 2)
void dist_kernel(const float* __restrict__ key, const float* __restrict__ sq,
                 float* __restrict__ dist)
{
    int b = blockIdx.z;
    const float* A  = key + (size_t)b * NPTS * C_;
    const float* sb = sq + b * NPTS;
    float* D = dist + (size_t)b * NPTS * NPTS;

    int t = blockIdx.x, bi = 0;
    while (t >= 16 - bi) { t -= 16 - bi; bi++; }
    int bj = bi + t;

    __shared__ __align__(16) float Asq[2][16][128];
    __shared__ __align__(16) float Wt[2][16][128];
    int tid = threadIdx.x;
    int tx = tid & 15, ty = tid >> 4;
    int m0 = bi * 128, n0 = bj * 128;
    int lr = tid >> 2;
    int lc = (tid & 3) << 2;

    int wf0 = (q32(lr >> 2) << 2) | (lr & 3);
    int wf1 = (q32((lr + 64) >> 2) << 2) | (lr & 3);
    int ra0 = q32(2 * ty) << 2;
    int ra1 = q32(2 * ty + 1) << 2;
    int qw0 = q32(2 * tx) << 2;
    int qw1 = q32(2 * tx + 1) << 2;

    ull acc[8][4] = {};
    float4 a0, a1, w0, w1;

#define D_STS(BF) { \
        Asq[BF][lc+0][wf0] = a0.x; Asq[BF][lc+1][wf0] = a0.y; \
        Asq[BF][lc+2][wf0] = a0.z; Asq[BF][lc+3][wf0] = a0.w; \
        Asq[BF][lc+0][wf1] = a1.x; Asq[BF][lc+1][wf1] = a1.y; \
        Asq[BF][lc+2][wf1] = a1.z; Asq[BF][lc+3][wf1] = a1.w; \
        Wt[BF][lc+0][wf0] = w0.x; Wt[BF][lc+1][wf0] = w0.y; \
        Wt[BF][lc+2][wf0] = w0.z; Wt[BF][lc+3][wf0] = w0.w; \
        Wt[BF][lc+0][wf1] = w1.x; Wt[BF][lc+1][wf1] = w1.y; \
        Wt[BF][lc+2][wf1] = w1.z; Wt[BF][lc+3][wf1] = w1.w; }

    a0 = *(const float4*)&A[(size_t)(m0 + lr)      * C_ + lc];
    a1 = *(const float4*)&A[(size_t)(m0 + lr + 64) * C_ + lc];
    w0 = *(const float4*)&A[(size_t)(n0 + lr)      * C_ + lc];
    w1 = *(const float4*)&A[(size_t)(n0 + lr + 64) * C_ + lc];
    D_STS(0)
    __syncthreads();

    const int nT = C_ >> 4;
    for (int it = 0; it < nT; it++) {
        int cur = it & 1;
        if (it + 1 < nT) {
            int k0 = (it + 1) << 4;
            a0 = *(const float4*)&A[(size_t)(m0 + lr)      * C_ + k0 + lc];
            a1 = *(const float4*)&A[(size_t)(m0 + lr + 64) * C_ + k0 + lc];
            w0 = *(const float4*)&A[(size_t)(n0 + lr)      * C_ + k0 + lc];
            w1 = *(const float4*)&A[(size_t)(n0 + lr + 64) * C_ + k0 + lc];
        }
        #pragma unroll
        for (int kk = 0; kk < 16; kk++) MAIN_FMA(Asq[cur], Wt[cur])
        if (it + 1 < nT) {
            int nb = cur ^ 1;
            __syncthreads();
            { int BF = nb; D_STS(BF) }
            __syncthreads();
        }
    }
#undef D_STS

    float f[8][8];
    #pragma unroll
    for (int i = 0; i < 8; i++)
        #pragma unroll
        for (int j = 0; j < 4; j++) {
            float2 p = unpk(acc[i][j]);
            f[i][2*j] = p.x; f[i][2*j+1] = p.y;
        }

    float sn[8], sm[8];
    *(float4*)(sn)     = *(const float4*)&sb[n0 + tx*8];
    *(float4*)(sn + 4) = *(const float4*)&sb[n0 + tx*8 + 4];
    *(float4*)(sm)     = *(const float4*)&sb[m0 + ty*8];
    *(float4*)(sm + 4) = *(const float4*)&sb[m0 + ty*8 + 4];

    #pragma unroll
    for (int i = 0; i < 8; i++) {
        float o[8];
        #pragma unroll
        for (int j = 0; j < 8; j++) o[j] = sm[i] + sn[j] - 2.f * f[i][j];
        size_t r = (size_t)(m0 + ty*8 + i) * NPTS + n0 + tx*8;
        *(float4*)&D[r]     = *(float4*)(o);
        *(float4*)&D[r + 4] = *(float4*)(o + 4);
    }
    if (bi != bj) {
        #pragma unroll
        for (int j = 0; j < 8; j++) {
            float o[8];
            #pragma unroll
            for (int i = 0; i < 8; i++) o[i] = sn[j] + sm[i] - 2.f * f[i][j];
            size_t r = (size_t)(n0 + tx*8 + j) * NPTS + m0 + ty*8;
            *(float4*)&D[r]     = *(float4*)(o);
            *(float4*)&D[r + 4] = *(float4*)(o + 4);
        }
    }
}

// ---------------- BN apply q/k/v + fused sq ----------------
__global__ __launch_bounds__(256)
void bnqkv_kernel(const float* __restrict__ Y, float* __restrict__ out,
                  const float* __restrict__ gq, const float* __restrict__ bq,
                  const float* __restrict__ gk, const float* __restrict__ bk,
                  const float* __restrict__ gv, const float* __restrict__ bv,
                  float* __restrict__ sqv)
{
    int blk = blockIdx.x;
    int slice = blk >> 12;
    int row   = blk & 4095;
    int d = threadIdx.x;
    const float* gamma = slice == 0 ? gq : slice == 1 ? gk : gv;
    const float* beta  = slice == 0 ? bq : slice == 1 ? bk : bv;
    float a, c;
    foldco(slice, d, INV_M1, gamma, beta, a, c);
    size_t e = (size_t)blk * 256 + d;
    float z = a * Y[e] + c;
    float o = lrelu(z);
    out[e] = o;

    if (slice == 1) {
        __shared__ float sh[8];
        float s = o * o;
        #pragma unroll
        for (int off = 16; off; off >>= 1) s += __shfl_down_sync(0xffffffffu, s, off);
        if ((d & 31) == 0) sh[d >> 5] = s;
        __syncthreads();
        if (d == 0) {
            float t = 0.f;
            #pragma unroll
            for (int w = 0; w < 8; w++) t += sh[w];
            sqv[row] = t;
        }
    }
}

// ---------------- top-32 ----------------
#define CE(i,j) { if (vr[j] < vr[i] || (vr[j] == vr[i] && idr[j] < idr[i])) { \
                    float tv = vr[i]; vr[i] = vr[j]; vr[j] = tv; \
                    int ti = idr[i]; idr[i] = idr[j]; idr[j] = ti; } }

__global__ __launch_bounds__(256)
void topk_kernel(const float* __restrict__ dist)
{
    int bn = blockIdx.x;
    const float* row = dist + (size_t)bn * NPTS;
    int t = threadIdx.x;
    int lane = t & 31, wrp = t >> 5;

    __shared__ float lv[8][32];
    __shared__ int   li[8][32];

    {
        float vr[8]; int idr[8];
        #pragma unroll
        for (int s = 0; s < 8; s++) {
            int j = wrp * 256 + s * 32 + lane;
            vr[s] = row[j]; idr[s] = j;
        }
        CE(0,1) CE(2,3) CE(4,5) CE(6,7)
        CE(0,2) CE(1,3) CE(4,6) CE(5,7)
        CE(1,2) CE(5,6)
        CE(0,4) CE(1,5) CE(2,6) CE(3,7)
        CE(2,4) CE(3,5)
        CE(1,2) CE(3,4) CE(5,6)

        float outv = FLT_MAX; int outi = 0x7fffffff;
        for (int sel = 0; sel < KNB; sel++) {
            float cv = vr[0]; int ci = idr[0];
            int myhead = idr[0];
            #pragma unroll
            for (int o = 16; o; o >>= 1) {
                float ov = __shfl_xor_sync(0xffffffffu, cv, o);
                int   oi = __shfl_xor_sync(0xffffffffu, ci, o);
                if (ov < cv || (ov == cv && oi < ci)) { cv = ov; ci = oi; }
            }
            if (lane == sel) { outv = cv; outi = ci; }
            if (myhead == ci) {
                #pragma unroll
                for (int s = 0; s < 7; s++) { vr[s] = vr[s+1]; idr[s] = idr[s+1]; }
                vr[7] = FLT_MAX; idr[7] = 0x7fffffff;
            }
        }
        lv[wrp][lane] = outv;
        li[wrp][lane] = outi;
    }
    __syncthreads();

    if (wrp == 0) {
        float vr[8]; int idr[8];
        #pragma unroll
        for (int j = 0; j < 8; j++) { vr[j] = lv[j][lane]; idr[j] = li[j][lane]; }
        CE(0,1) CE(2,3) CE(4,5) CE(6,7)
        CE(0,2) CE(1,3) CE(4,6) CE(5,7)
        CE(1,2) CE(5,6)
        CE(0,4) CE(1,5) CE(2,6) CE(3,7)
        CE(2,4) CE(3,5)
        CE(1,2) CE(3,4) CE(5,6)

        for (int sel = 0; sel < KNB; sel++) {
            float cv = vr[0]; int ci = idr[0];
            int myhead = idr[0];
            #pragma unroll
            for (int o = 16; o; o >>= 1) {
                float ov = __shfl_xor_sync(0xffffffffu, cv, o);
                int   oi = __shfl_xor_sync(0xffffffffu, ci, o);
                if (ov < cv || (ov == cv && oi < ci)) { cv = ov; ci = oi; }
            }
            if (lane == 0) g_idx[(size_t)bn * KNB + sel] = ci;
            if (myhead == ci) {
                #pragma unroll
                for (int s = 0; s < 7; s++) { vr[s] = vr[s+1]; idr[s] = idr[s+1]; }
                vr[7] = FLT_MAX; idr[7] = 0x7fffffff;
            }
        }
    }
}

// ---------------- stats infra ----------------
__global__ void zero_all_stats()
{
    int i = blockIdx.x * 256 + threadIdx.x;
    if (i < 8 * HID) { ((double*)g_dsum)[i] = 0.0; ((double*)g_dsum2)[i] = 0.0; }
}

// ---------------- posb stats via moments ----------------
__global__ __launch_bounds__(256)
void pbstats_kernel(const float* __restrict__ P)
{
    int d = threadIdx.x;
    float s = 0.f, s2 = 0.f;
    for (int gidx = 0; gidx < 16; gidx++) {
        int bn = blockIdx.x * 16 + gidx;
        int b  = bn >> 11;
        float pn = P[(size_t)bn * C_ + d];
        const int* ip = &g_idx[(size_t)bn * KNB];
        float A1 = 0.f, A2 = 0.f;
        #pragma unroll 4
        for (int k = 0; k < KNB; k++) {
            int jg = (b << 11) + ip[k];
            float v = P[(size_t)jg * C_ + d];
            A1 += v; A2 += v * v;
        }
        s  += A1 - 32.f * pn;
        s2 += A2 - 2.f * pn * A1 + 32.f * pn * pn;
    }
    atomicAdd(&g_dsum[ST_PB][d],  (double)s);
    atomicAdd(&g_dsum2[ST_PB][d], (double)s2);
}

// ---------------- final BN+silu+residual ----------------
__global__ void bn_silu_res_apply(const float* __restrict__ Y, const float* __restrict__ res,
                                  float* __restrict__ out,
                                  const float* __restrict__ gm2, const float* __restrict__ bm2)
{
    int d = threadIdx.x;
    float a, c;
    foldco(ST_M2, d, INV_M1, gm2, bm2, a, c);
    size_t e = (size_t)blockIdx.x * 256 + d;
    float z = a * Y[e] + c;
    out[e] = res[e] + z / (1.f + expf(-z));
}

// ---------------- vec1: PIPELINED gather GEMM ----------------
__global__ __launch_bounds__(256)
void vec1_kernel(const float* __restrict__ qb, const float* __restrict__ kb,
                 const float* __restrict__ P,  const float* __restrict__ We1,
                 const float* __restrict__ gpb, const float* __restrict__ bpb,
                 float* __restrict__ s1)
{
    __shared__ __align__(16) float As[2][16][128];
    __shared__ __align__(16) float Wsd[2][16][64];
    __shared__ __align__(16) float spa[C_], spc[C_];
    __shared__ int sj[128];
    __shared__ float cs[8][32], cs2[8][32];
    int tid = threadIdx.x;
    int m0 = blockIdx.x * 128;
    foldco(ST_PB, tid, INV_M2, gpb, bpb, spa[tid], spc[tid]);
    if (tid < 128) sj[tid] = g_idx[m0 + tid];
    __syncthreads();

    int tx = tid & 15, ty = tid >> 4;
    int lr = tid >> 2;
    int lc = (tid & 3) << 2;
    int r0 = m0 + lr,      bn0 = r0 >> 5, b0 = r0 >> 16;
    int r1 = m0 + lr + 64, bn1 = r1 >> 5, b1 = r1 >> 16;
    int jg0 = (b0 << 11) + sj[lr];
    int jg1 = (b1 << 11) + sj[lr + 64];
    ull acc[4][2] = {};

    float4 kf0, qf0, pj0, pn0, kf1, qf1, pj1, pn1;
    float ws0, ws1;

#define V_LOAD(K0) { \
        kf0 = *(const float4*)&kb[(size_t)jg0 * C_ + (K0) + lc]; \
        qf0 = *(const float4*)&qb[(size_t)bn0 * C_ + (K0) + lc]; \
        pj0 = *(const float4*)&P [(size_t)jg0 * C_ + (K0) + lc]; \
        pn0 = *(const float4*)&P [(size_t)bn0 * C_ + (K0) + lc]; \
        kf1 = *(const float4*)&kb[(size_t)jg1 * C_ + (K0) + lc]; \
        qf1 = *(const float4*)&qb[(size_t)bn1 * C_ + (K0) + lc]; \
        pj1 = *(const float4*)&P [(size_t)jg1 * C_ + (K0) + lc]; \
        pn1 = *(const float4*)&P [(size_t)bn1 * C_ + (K0) + lc]; \
        ws0 = We1[(size_t)(tid & 31) * C_ + (K0) + (tid >> 5)]; \
        ws1 = We1[(size_t)(tid & 31) * C_ + (K0) + (tid >> 5) + 8]; }
#define V_STS(BF, K0) { \
        float4 pa = *(const float4*)&spa[(K0) + lc]; \
        float4 pc = *(const float4*)&spc[(K0) + lc]; \
        As[BF][lc+0][lr] = kf0.x - qf0.x + lrelu(pa.x * (pj0.x - pn0.x) + pc.x); \
        As[BF][lc+1][lr] = kf0.y - qf0.y + lrelu(pa.y * (pj0.y - pn0.y) + pc.y); \
        As[BF][lc+2][lr] = kf0.z - qf0.z + lrelu(pa.z * (pj0.z - pn0.z) + pc.z); \
        As[BF][lc+3][lr] = kf0.w - qf0.w + lrelu(pa.w * (pj0.w - pn0.w) + pc.w); \
        As[BF][lc+0][lr+64] = kf1.x - qf1.x + lrelu(pa.x * (pj1.x - pn1.x) + pc.x); \
        As[BF][lc+1][lr+64] = kf1.y - qf1.y + lrelu(pa.y * (pj1.y - pn1.y) + pc.y); \
        As[BF][lc+2][lr+64] = kf1.z - qf1.z + lrelu(pa.z * (pj1.z - pn1.z) + pc.z); \
        As[BF][lc+3][lr+64] = kf1.w - qf1.w + lrelu(pa.w * (pj1.w - pn1.w) + pc.w); \
        *(ull*)&Wsd[BF][tid >> 5][2*(tid & 31)]       = dup2(ws0); \
        *(ull*)&Wsd[BF][(tid >> 5) + 8][2*(tid & 31)] = dup2(ws1); }

    V_LOAD(0)
    V_STS(0, 0)
    __syncthreads();
    const int nT = C_ >> 4;
    for (int it = 0; it < nT; it++) {
        int cur = it & 1;
        if (it + 1 < nT) V_LOAD((it + 1) << 4)
        #pragma unroll
        for (int kk = 0; kk < 16; kk++) {
            ulonglong2 aA = *(const ulonglong2*)&As[cur][kk][ty*8];
            ulonglong2 aB = *(const ulonglong2*)&As[cur][kk][ty*8 + 4];
            ull ap[4] = { aA.x, aA.y, aB.x, aB.y };
            ulonglong2 wv = *(const ulonglong2*)&Wsd[cur][kk][4*tx];
            #pragma unroll
            for (int i2 = 0; i2 < 4; i2++) {
                fma2(acc[i2][0], ap[i2], wv.x);
                fma2(acc[i2][1], ap[i2], wv.y);
            }
        }
        if (it + 1 < nT) {
            __syncthreads();
            V_STS(cur ^ 1, (it + 1) << 4)
            __syncthreads();
        }
    }
#undef V_LOAD
#undef V_STS

    #pragma unroll
    for (int i2 = 0; i2 < 4; i2++) {
        float2 p0 = unpk(acc[i2][0]), p1 = unpk(acc[i2][1]);
        size_t w0 = (size_t)(m0 + ty*8 + 2*i2) * CPH + tx*2;
        s1[w0]           = p0.x; s1[w0 + 1]       = p1.x;
        s1[w0 + CPH]     = p0.y; s1[w0 + CPH + 1] = p1.y;
    }
    float ps[2], ps2[2];
    #pragma unroll
    for (int j = 0; j < 2; j++) {
        ull s = add2(add2(acc[0][j], acc[1][j]), add2(acc[2][j], acc[3][j]));
        ull q = add2(add2(mul2(acc[0][j], acc[0][j]), mul2(acc[1][j], acc[1][j])),
                     add2(mul2(acc[2][j], acc[2][j]), mul2(acc[3][j], acc[3][j])));
        float2 fs = unpk(s), fq = unpk(q);
        ps[j] = fs.x + fs.y; ps2[j] = fq.x + fq.y;
    }
    ps[0]  += __shfl_down_sync(0xffffffffu, ps[0], 16);
    ps[1]  += __shfl_down_sync(0xffffffffu, ps[1], 16);
    ps2[0] += __shfl_down_sync(0xffffffffu, ps2[0], 16);
    ps2[1] += __shfl_down_sync(0xffffffffu, ps2[1], 16);
    int lane = tid & 31, wrp = tid >> 5;
    if (lane < 16) {
        cs[wrp][tx*2]      = ps[0];  cs[wrp][tx*2 + 1]  = ps[1];
        cs2[wrp][tx*2]     = ps2[0]; cs2[wrp][tx*2 + 1] = ps2[1];
    }
    __syncthreads();
    if (tid < 32) {
        double s = 0.0, s2 = 0.0;
        #pragma unroll
        for (int w = 0; w < 8; w++) { s += cs[w][tid]; s2 += cs2[w][tid]; }
        atomicAdd(&g_dsum[ST_S1][tid], s);
        atomicAdd(&g_dsum2[ST_S1][tid], s2);
    }
}

// ---------------- vec2 ----------------
__global__ __launch_bounds__(256)
void vec2_kernel(const float* __restrict__ s1, const float* __restrict__ We2,
                 const float* __restrict__ ge1, const float* __restrict__ be1,
                 float* __restrict__ s2)
{
    __shared__ __align__(16) float As[16][128];
    __shared__ __align__(16) float Wsd[16][64];
    __shared__ __align__(16) float sfa[CPH], sfc[CPH];
    __shared__ float cs[8][32], cs2[8][32];
    int tid = threadIdx.x;
    int m0 = blockIdx.x * 128;
    if (tid < CPH) foldco(ST_S1, tid, INV_M2, ge1, be1, sfa[tid], sfc[tid]);
    __syncthreads();

    int tx = tid & 15, ty = tid >> 4;
    int lr = tid >> 2;
    int lc = (tid & 3) << 2;
    ull acc[4][2] = {};

    for (int k0 = 0; k0 < CPH; k0 += 16) {
        #pragma unroll
        for (int h = 0; h < 2; h++) {
            int rr = h ? lr + 64 : lr;
            float4 y  = *(const float4*)&s1[(size_t)(m0 + rr) * CPH + k0 + lc];
            float4 aa = *(const float4*)&sfa[k0 + lc];
            float4 cc = *(const float4*)&sfc[k0 + lc];
            As[lc+0][rr] = lrelu(aa.x * y.x + cc.x);
            As[lc+1][rr] = lrelu(aa.y * y.y + cc.y);
            As[lc+2][rr] = lrelu(aa.z * y.z + cc.z);
            As[lc+3][rr] = lrelu(aa.w * y.w + cc.w);
        }
        {
            int i0 = tid;
            *(ull*)&Wsd[i0 >> 5][2*(i0 & 31)] = dup2(We2[(size_t)(i0 & 31) * CPH + k0 + (i0 >> 5)]);
            int i1 = tid + 256;
            *(ull*)&Wsd[i1 >> 5][2*(i1 & 31)] = dup2(We2[(size_t)(i1 & 31) * CPH + k0 + (i1 >> 5)]);
        }
        __syncthreads();
        #pragma unroll
        for (int kk = 0; kk < 16; kk++) {
            ulonglong2 aA = *(const ulonglong2*)&As[kk][ty*8];
            ulonglong2 aB = *(const ulonglong2*)&As[kk][ty*8 + 4];
            ull ap[4] = { aA.x, aA.y, aB.x, aB.y };
            ulonglong2 wv = *(const ulonglong2*)&Wsd[kk][4*tx];
            #pragma unroll
            for (int i2 = 0; i2 < 4; i2++) {
                fma2(acc[i2][0], ap[i2], wv.x);
                fma2(acc[i2][1], ap[i2], wv.y);
            }
        }
        __syncthreads();
    }
    #pragma unroll
    for (int i2 = 0; i2 < 4; i2++) {
        float2 p0 = unpk(acc[i2][0]), p1 = unpk(acc[i2][1]);
        size_t w0 = (size_t)(m0 + ty*8 + 2*i2) * CPH + tx*2;
        s2[w0]           = p0.x; s2[w0 + 1]       = p1.x;
        s2[w0 + CPH]     = p0.y; s2[w0 + CPH + 1] = p1.y;
    }
    float ps[2], ps2[2];
    #pragma unroll
    for (int j = 0; j < 2; j++) {
        ull s = add2(add2(acc[0][j], acc[1][j]), add2(acc[2][j], acc[3][j]));
        ull q = add2(add2(mul2(acc[0][j], acc[0][j]), mul2(acc[1][j], acc[1][j])),
                     add2(mul2(acc[2][j], acc[2][j]), mul2(acc[3][j], acc[3][j])));
        float2 fs = unpk(s), fq = unpk(q);
        ps[j] = fs.x + fs.y; ps2[j] = fq.x + fq.y;
    }
    ps[0]  += __shfl_down_sync(0xffffffffu, ps[0], 16);
    ps[1]  += __shfl_down_sync(0xffffffffu, ps[1], 16);
    ps2[0] += __shfl_down_sync(0xffffffffu, ps2[0], 16);
    ps2[1] += __shfl_down_sync(0xffffffffu, ps2[1], 16);
    int lane = tid & 31, wrp = tid >> 5;
    if (lane < 16) {
        cs[wrp][tx*2]      = ps[0];  cs[wrp][tx*2 + 1]  = ps[1];
        cs2[wrp][tx*2]     = ps2[0]; cs2[wrp][tx*2 + 1] = ps2[1];
    }
    __syncthreads();
    if (tid < 32) {
        double s = 0.0, s2 = 0.0;
        #pragma unroll
        for (int w = 0; w < 8; w++) { s += cs[w][tid]; s2 += cs2[w][tid]; }
        atomicAdd(&g_dsum[ST_S2][tid], s);
        atomicAdd(&g_dsum2[ST_S2][tid], s2);
    }
}

// ---------------- attention ----------------
__global__ __launch_bounds__(256)
void attn_kernel(const float* __restrict__ x, const float* __restrict__ s2,
                 const float* __restrict__ vb, const float* __restrict__ P,
                 const float* __restrict__ ge2, const float* __restrict__ be2,
                 const float* __restrict__ gpb, const float* __restrict__ bpb,
                 float* __restrict__ xattn)
{
    int bn = blockIdx.x;
    int t = threadIdx.x;
    __shared__ float soft[KNB][CPH + 1];
    __shared__ float ssa[CPH], ssc[CPH];
    __shared__ int sj[KNB];
    if (t < CPH) foldco(ST_S2, t, INV_M2, ge2, be2, ssa[t], ssc[t]);
    if (t >= 32 && t < 64) sj[t - 32] = g_idx[(size_t)bn * KNB + t - 32];
    float pa, pc;
    foldco(ST_PB, t, INV_M2, gpb, bpb, pa, pc);
    __syncthreads();

    size_t base = (size_t)bn * KNB * CPH;
    for (int e = t; e < KNB * CPH; e += 256) {
        int g = e & 31;
        float y = s2[base + e];
        soft[e >> 5][g] = lrelu(ssa[g] * y + ssc[g]);
    }
    __syncthreads();
    if (t < CPH) {
        float mx = -FLT_MAX;
        #pragma unroll
        for (int k = 0; k < KNB; k++) mx = fmaxf(mx, soft[k][t]);
        float s = 0.f;
        #pragma unroll
        for (int k = 0; k < KNB; k++) { float ev = expf(soft[k][t] - mx); soft[k][t] = ev; s += ev; }
        float inv = 1.f / s;
        #pragma unroll
        for (int k = 0; k < KNB; k++) soft[k][t] *= inv;
    }
    __syncthreads();

    int c = t, g = t >> 3;
    int b = bn >> 11;
    float pn = P[(size_t)bn * C_ + c];
    float acc = 0.f;
    #pragma unroll
    for (int k = 0; k < KNB; k++) {
        int jg = (b << 11) + sj[k];
        float posb = lrelu(pa * (P[(size_t)jg * C_ + c] - pn) + pc);
        acc += (vb[(size_t)jg * C_ + c] + posb) * soft[k][g];
    }
    size_t o = (size_t)bn * C_ + c;
    xattn[o] = x[o] + acc;
}

extern "C" void kernel_launch(void* const* d_in, const int* in_sizes, int n_in,
                              void* d_out, int out_size)
{
    const float* x   = (const float*)d_in[0];
    const float* pos = (const float*)d_in[1];
    const float* Wq  = (const float*)d_in[2];
    const float* gq  = (const float*)d_in[3];
    const float* bq  = (const float*)d_in[4];
    const float* Wk  = (const float*)d_in[5];
    const float* gk  = (const float*)d_in[6];
    const float* bk  = (const float*)d_in[7];
    const float* Wv  = (const float*)d_in[8];
    const float* gv  = (const float*)d_in[9];
    const float* bv  = (const float*)d_in[10];
    const float* Wpb = (const float*)d_in[11];
    const float* gpb = (const float*)d_in[12];
    const float* bpb = (const float*)d_in[13];
    const float* We1 = (const float*)d_in[14];
    const float* ge1 = (const float*)d_in[15];
    const float* be1 = (const float*)d_in[16];
    const float* We2 = (const float*)d_in[17];
    const float* ge2 = (const float*)d_in[18];
    const float* be2 = (const float*)d_in[19];
    const float* Wm1 = (const float*)d_in[20];
    const float* gm1 = (const float*)d_in[21];
    const float* bm1 = (const float*)d_in[22];
    const float* Wm2 = (const float*)d_in[23];
    const float* gm2 = (const float*)d_in[24];
    const float* bm2 = (const float*)d_in[25];
    float* out = (float*)d_out;

    void* p;
    float *qkv, *tmp, *sqv, *dist, *s1, *s2, *xatt;
    cudaGetSymbolAddress(&p, g_qkv);   qkv  = (float*)p;
    cudaGetSymbolAddress(&p, g_tmp4);  tmp  = (float*)p;
    cudaGetSymbolAddress(&p, g_sqv);   sqv  = (float*)p;
    cudaGetSymbolAddress(&p, g_dist);  dist = (float*)p;
    cudaGetSymbolAddress(&p, g_s1);    s1   = (float*)p;
    cudaGetSymbolAddress(&p, g_s2);    s2   = (float*)p;
    cudaGetSymbolAddress(&p, g_xattn); xatt = (float*)p;

    const size_t SL = (size_t)M1 * C_;
    float* t0 = tmp;
    float* t1 = tmp + SL;
    float* t2 = tmp + 2*SL;
    float* t3 = tmp + 3*SL;
    float* qb = qkv;
    float* kb = qkv + SL;
    float* vb = qkv + 2*SL;

    zero_all_stats<<<16, 256>>>();
    {
        Gemm4 g = { { x, x, x, pos }, { Wq, Wk, Wv, Wpb }, { t0, t1, t2, t3 },
                    { ST_Q, ST_K, ST_V, -1 } };
        gemm128p_kernel<<<dim3(C_/128, M1/128, 4), 256>>>(g, C_, C_);
    }
    bnqkv_kernel<<<3 * M1, 256>>>(tmp, qkv, gq, bq, gk, bk, gv, bv, sqv);
    dist_kernel<<<dim3(136, 1, B_), 256>>>(kb, sqv, dist);
    topk_kernel<<<M1, 256>>>(dist);
    pbstats_kernel<<<256, 256>>>(t3);
    vec1_kernel<<<M2/128, 256>>>(qb, kb, t3, We1, gpb, bpb, s1);
    vec2_kernel<<<M2/128, 256>>>(s1, We2, ge1, be1, s2);
    attn_kernel<<<M1, 256>>>(x, s2, vb, t3, ge2, be2, gpb, bpb, xatt);
    {
        Gemm4 g = { { xatt, 0, 0, 0 }, { Wm1, 0, 0, 0 }, { t0, 0, 0, 0 },
                    { ST_M1, -1, -1, -1 } };
        gemm128p_kernel<<<dim3(HID/128, M1/128, 1), 256>>>(g, HID, C_);
    }
    {
        Gemm4 g = { { t0, 0, 0, 0 }, { Wm2, 0, 0, 0 }, { t2, 0, 0, 0 },
                    { ST_M2, -1, -1, -1 } };
        gemm128_kernel<<<dim3(C_/128, M1/128, 1), 256>>>(g, C_, HID, 1, gm1, bm1);
    }
    bn_silu_res_apply<<<M1, 256>>>(t2, xatt, out, gm2, bm2);
}

// round 15
// speedup vs baseline: 1.1022x; 1.0024x over previous
#include <cuda_runtime.h>
#include <math.h>
#include <float.h>

#define B_   2
#define NPTS 2048
#define C_   256
#define KNB  32
#define HID  512
#define CPH  32
#define M1   (B_*NPTS)        // 4096
#define M2   (B_*NPTS*KNB)    // 131072
#define EPSB 1e-5f

#define ST_Q  0
#define ST_K  1
#define ST_V  2
#define ST_PB 3
#define ST_S1 4
#define ST_S2 5
#define ST_M1 6
#define ST_M2 7

#define INV_M1 (1.0/4096.0)
#define INV_M2 (1.0/131072.0)

typedef unsigned long long ull;

// ---------------- device scratch ----------------
__device__ float g_qkv[3*M1*C_];
__device__ float g_tmp4[(size_t)M1*C_*4];
__device__ float g_sqv[M1];
__device__ float g_dist[(size_t)B_*NPTS*NPTS];
__device__ int   g_idx[M2];
__device__ float g_s1[(size_t)M2*CPH];
__device__ float g_s2[(size_t)M2*CPH];
__device__ float g_xattn[M1*C_];
__device__ double g_dsum[8][HID];
__device__ double g_dsum2[8][HID];

__device__ __forceinline__ float lrelu(float z) { return z >= 0.f ? z : 0.2f * z; }

__device__ __forceinline__ void foldco(int stage, int d, double invM,
                                       const float* __restrict__ gamma,
                                       const float* __restrict__ beta,
                                       float& a, float& c)
{
    double m = g_dsum[stage][d] * invM;
    double v = g_dsum2[stage][d] * invM - m * m;
    if (v < 0.0) v = 0.0;
    a = gamma[d] * rsqrtf((float)v + EPSB);
    c = beta[d] - (float)m * a;
}

// ---------------- packed f32x2 helpers ----------------
__device__ __forceinline__ void fma2(ull& d, ull a, ull b) {
    asm("fma.rn.f32x2 %0, %1, %2, %0;" : "+l"(d) : "l"(a), "l"(b));
}
__device__ __forceinline__ ull add2(ull a, ull b) {
    ull d; asm("add.rn.f32x2 %0, %1, %2;" : "=l"(d) : "l"(a), "l"(b)); return d;
}
__device__ __forceinline__ ull mul2(ull a, ull b) {
    ull d; asm("mul.rn.f32x2 %0, %1, %2;" : "=l"(d) : "l"(a), "l"(b)); return d;
}
__device__ __forceinline__ ull dup2(float x) {
    ull r; asm("mov.b64 %0, {%1, %1};" : "=l"(r) : "f"(x)); return r;
}
__device__ __forceinline__ float2 unpk(ull v) {
    float2 f; asm("mov.b64 {%0, %1}, %2;" : "=f"(f.x), "=f"(f.y) : "l"(v)); return f;
}

// quad XOR swizzle for 32-quad rows (128 floats)
__device__ __forceinline__ int q32(int p) { return p ^ (p >> 3); }

struct Gemm4 {
    const float* A[4];
    const float* W[4];
    float*       C[4];
    int          stage[4];
};

// common per-kk compute: A read as 2 float4 (broadcast), dup in regs; W pair-reads
#define MAIN_FMA(ASQ, WTQ) { \
        float4 Af0 = *(const float4*)&ASQ[kk][ra0]; \
        float4 Af1 = *(const float4*)&ASQ[kk][ra1]; \
        ull ap[8] = { dup2(Af0.x), dup2(Af0.y), dup2(Af0.z), dup2(Af0.w), \
                      dup2(Af1.x), dup2(Af1.y), dup2(Af1.z), dup2(Af1.w) }; \
        ulonglong2 W0 = *(const ulonglong2*)&WTQ[kk][qw0]; \
        ulonglong2 W1 = *(const ulonglong2*)&WTQ[kk][qw1]; \
        ull wp[4] = { W0.x, W0.y, W1.x, W1.y }; \
        _Pragma("unroll") \
        for (int i = 0; i < 8; i++) \
            _Pragma("unroll") \
            for (int j = 0; j < 4; j++) \
                fma2(acc[i][j], ap[i], wp[j]); }

// ================= PIPELINED FMA2 GEMM, A un-duplicated =================
__global__ __launch_bounds__(256, 2)
void gemm128p_kernel(Gemm4 g, int N, int K)
{
    __shared__ __align__(16) float Asq[2][16][128];   // 16 KB
    __shared__ __align__(16) float Wt[2][16][128];    // 16 KB
    int z = blockIdx.z;
    const float* A = g.A[z];
    const float* W = g.W[z];
    float*       C = g.C[z];
    int stage = g.stage[z];
    int tid = threadIdx.x;

    int tx = tid & 15, ty = tid >> 4;
    int m0 = blockIdx.y * 128, n0 = blockIdx.x * 128;
    int lr = tid >> 2;
    int lc = (tid & 3) << 2;

    int wf0 = (q32(lr >> 2) << 2) | (lr & 3);
    int wf1 = (q32((lr + 64) >> 2) << 2) | (lr & 3);
    int ra0 = q32(2 * ty) << 2;
    int ra1 = q32(2 * ty + 1) << 2;
    int qw0 = q32(2 * tx) << 2;
    int qw1 = q32(2 * tx + 1) << 2;

    ull acc[8][4] = {};
    float4 a0, a1, w0, w1;

#define P_STS(BF) { \
        Asq[BF][lc+0][wf0] = a0.x; Asq[BF][lc+1][wf0] = a0.y; \
        Asq[BF][lc+2][wf0] = a0.z; Asq[BF][lc+3][wf0] = a0.w; \
        Asq[BF][lc+0][wf1] = a1.x; Asq[BF][lc+1][wf1] = a1.y; \
        Asq[BF][lc+2][wf1] = a1.z; Asq[BF][lc+3][wf1] = a1.w; \
        Wt[BF][lc+0][wf0] = w0.x; Wt[BF][lc+1][wf0] = w0.y; \
        Wt[BF][lc+2][wf0] = w0.z; Wt[BF][lc+3][wf0] = w0.w; \
        Wt[BF][lc+0][wf1] = w1.x; Wt[BF][lc+1][wf1] = w1.y; \
        Wt[BF][lc+2][wf1] = w1.z; Wt[BF][lc+3][wf1] = w1.w; }

    a0 = *(const float4*)&A[(size_t)(m0 + lr)      * K + lc];
    a1 = *(const float4*)&A[(size_t)(m0 + lr + 64) * K + lc];
    w0 = *(const float4*)&W[(size_t)(n0 + lr)      * K + lc];
    w1 = *(const float4*)&W[(size_t)(n0 + lr + 64) * K + lc];
    P_STS(0)
    __syncthreads();

    const int nT = K >> 4;
    for (int it = 0; it < nT; it++) {
        int cur = it & 1;
        if (it + 1 < nT) {
            int k0 = (it + 1) << 4;
            a0 = *(const float4*)&A[(size_t)(m0 + lr)      * K + k0 + lc];
            a1 = *(const float4*)&A[(size_t)(m0 + lr + 64) * K + k0 + lc];
            w0 = *(const float4*)&W[(size_t)(n0 + lr)      * K + k0 + lc];
            w1 = *(const float4*)&W[(size_t)(n0 + lr + 64) * K + k0 + lc];
        }
        #pragma unroll
        for (int kk = 0; kk < 16; kk++) MAIN_FMA(Asq[cur], Wt[cur])
        if (it + 1 < nT) {
            int nb = cur ^ 1;
            __syncthreads();
            { int BF = nb; P_STS(BF) }
            __syncthreads();
        }
    }
#undef P_STS

    #pragma unroll
    for (int i = 0; i < 8; i++) {
        float o[8];
        #pragma unroll
        for (int j = 0; j < 4; j++) {
            float2 p = unpk(acc[i][j]);
            o[2*j] = p.x; o[2*j+1] = p.y;
        }
        size_t r = (size_t)(m0 + ty*8 + i) * N + n0 + tx*8;
        *(float4*)&C[r]     = *(float4*)(o);
        *(float4*)&C[r + 4] = *(float4*)(o + 4);
    }

    if (stage >= 0) {
        float ps[8], ps2[8];
        #pragma unroll
        for (int j = 0; j < 4; j++) {
            ull s = add2(add2(add2(acc[0][j], acc[1][j]), add2(acc[2][j], acc[3][j])),
                         add2(add2(acc[4][j], acc[5][j]), add2(acc[6][j], acc[7][j])));
            ull q = add2(add2(add2(mul2(acc[0][j],acc[0][j]), mul2(acc[1][j],acc[1][j])),
                              add2(mul2(acc[2][j],acc[2][j]), mul2(acc[3][j],acc[3][j]))),
                         add2(add2(mul2(acc[4][j],acc[4][j]), mul2(acc[5][j],acc[5][j])),
                              add2(mul2(acc[6][j],acc[6][j]), mul2(acc[7][j],acc[7][j]))));
            float2 fs = unpk(s), fq = unpk(q);
            ps[2*j] = fs.x; ps[2*j+1] = fs.y;
            ps2[2*j] = fq.x; ps2[2*j+1] = fq.y;
        }
        #pragma unroll
        for (int j = 0; j < 8; j++) {
            ps[j]  += __shfl_down_sync(0xffffffffu, ps[j], 16);
            ps2[j] += __shfl_down_sync(0xffffffffu, ps2[j], 16);
        }
        float (*red)[128] = (float(*)[128])&Asq[0][0][0];
        int lane = tid & 31, wrp = tid >> 5;
        __syncthreads();
        if (lane < 16) {
            #pragma unroll
            for (int j = 0; j < 8; j++) {
                red[wrp][tx*8 + j]     = ps[j];
                red[wrp + 8][tx*8 + j] = ps2[j];
            }
        }
        __syncthreads();
        if (tid < 128) {
            double s = 0.0, s2 = 0.0;
            #pragma unroll
            for (int w = 0; w < 8; w++) { s += red[w][tid]; s2 += red[w + 8][tid]; }
            atomicAdd(&g_dsum[stage][n0 + tid], s);
            atomicAdd(&g_dsum2[stage][n0 + tid], s2);
        }
    }
}

// ================= single-buffer gemm, dosilu fused, A un-duplicated (MLP2) =================
__global__ __launch_bounds__(256, 2)
void gemm128_kernel(Gemm4 g, int N, int K, int dosilu,
                    const float* __restrict__ fg, const float* __restrict__ fb)
{
    __shared__ __align__(16) float Asq[16][128];
    __shared__ __align__(16) float Wt[16][128];
    __shared__ float sfa[HID], sfc[HID];
    int z = blockIdx.z;
    const float* A = g.A[z];
    const float* W = g.W[z];
    float*       C = g.C[z];
    int stage = g.stage[z];
    int tid = threadIdx.x;

    if (dosilu) {
        for (int d = tid; d < K; d += 256)
            foldco(ST_M1, d, INV_M1, fg, fb, sfa[d], sfc[d]);
        __syncthreads();
    }

    int tx = tid & 15, ty = tid >> 4;
    int m0 = blockIdx.y * 128, n0 = blockIdx.x * 128;
    int lr = tid >> 2;
    int lc = (tid & 3) << 2;

    int wf0 = (q32(lr >> 2) << 2) | (lr & 3);
    int wf1 = (q32((lr + 64) >> 2) << 2) | (lr & 3);
    int ra0 = q32(2 * ty) << 2;
    int ra1 = q32(2 * ty + 1) << 2;
    int qw0 = q32(2 * tx) << 2;
    int qw1 = q32(2 * tx + 1) << 2;

    ull acc[8][4] = {};

    for (int k0 = 0; k0 < K; k0 += 16) {
        float4 a0 = *(const float4*)&A[(size_t)(m0 + lr)      * K + k0 + lc];
        float4 a1 = *(const float4*)&A[(size_t)(m0 + lr + 64) * K + k0 + lc];
        if (dosilu) {
            #pragma unroll
            for (int i = 0; i < 4; i++) {
                float aa = sfa[k0 + lc + i];
                float cc = sfc[k0 + lc + i];
                float* pz = (i==0)?&a0.x:(i==1)?&a0.y:(i==2)?&a0.z:&a0.w;
                float* pw = (i==0)?&a1.x:(i==1)?&a1.y:(i==2)?&a1.z:&a1.w;
                float z0 = aa * (*pz) + cc; *pz = z0 / (1.f + __expf(-z0));
                float z1 = aa * (*pw) + cc; *pw = z1 / (1.f + __expf(-z1));
            }
        }
        float4 w0 = *(const float4*)&W[(size_t)(n0 + lr)      * K + k0 + lc];
        float4 w1 = *(const float4*)&W[(size_t)(n0 + lr + 64) * K + k0 + lc];
        Asq[lc+0][wf0] = a0.x; Asq[lc+1][wf0] = a0.y; Asq[lc+2][wf0] = a0.z; Asq[lc+3][wf0] = a0.w;
        Asq[lc+0][wf1] = a1.x; Asq[lc+1][wf1] = a1.y; Asq[lc+2][wf1] = a1.z; Asq[lc+3][wf1] = a1.w;
        Wt[lc+0][wf0] = w0.x; Wt[lc+1][wf0] = w0.y; Wt[lc+2][wf0] = w0.z; Wt[lc+3][wf0] = w0.w;
        Wt[lc+0][wf1] = w1.x; Wt[lc+1][wf1] = w1.y; Wt[lc+2][wf1] = w1.z; Wt[lc+3][wf1] = w1.w;
        __syncthreads();
        #pragma unroll
        for (int kk = 0; kk < 16; kk++) MAIN_FMA(Asq, Wt)
        __syncthreads();
    }

    #pragma unroll
    for (int i = 0; i < 8; i++) {
        float o[8];
        #pragma unroll
        for (int j = 0; j < 4; j++) {
            float2 p = unpk(acc[i][j]);
            o[2*j] = p.x; o[2*j+1] = p.y;
        }
        size_t r = (size_t)(m0 + ty*8 + i) * N + n0 + tx*8;
        *(float4*)&C[r]     = *(float4*)(o);
        *(float4*)&C[r + 4] = *(float4*)(o + 4);
    }

    if (stage >= 0) {
        float ps[8], ps2[8];
        #pragma unroll
        for (int j = 0; j < 4; j++) {
            ull s = add2(add2(add2(acc[0][j], acc[1][j]), add2(acc[2][j], acc[3][j])),
                         add2(add2(acc[4][j], acc[5][j]), add2(acc[6][j], acc[7][j])));
            ull q = add2(add2(add2(mul2(acc[0][j],acc[0][j]), mul2(acc[1][j],acc[1][j])),
                              add2(mul2(acc[2][j],acc[2][j]), mul2(acc[3][j],acc[3][j]))),
                         add2(add2(mul2(acc[4][j],acc[4][j]), mul2(acc[5][j],acc[5][j])),
                              add2(mul2(acc[6][j],acc[6][j]), mul2(acc[7][j],acc[7][j]))));
            float2 fs = unpk(s), fq = unpk(q);
            ps[2*j] = fs.x; ps[2*j+1] = fs.y;
            ps2[2*j] = fq.x; ps2[2*j+1] = fq.y;
        }
        #pragma unroll
        for (int j = 0; j < 8; j++) {
            ps[j]  += __shfl_down_sync(0xffffffffu, ps[j], 16);
            ps2[j] += __shfl_down_sync(0xffffffffu, ps2[j], 16);
        }
        float (*red)[128] = (float(*)[128])&Asq[0][0];
        int lane = tid & 31, wrp = tid >> 5;
        __syncthreads();
        if (lane < 16) {
            #pragma unroll
            for (int j = 0; j < 8; j++) {
                red[wrp][tx*8 + j]     = ps[j];
                red[wrp + 8][tx*8 + j] = ps2[j];
            }
        }
        __syncthreads();
        if (tid < 128) {
            double s = 0.0, s2 = 0.0;
            #pragma unroll
            for (int w = 0; w < 8; w++) { s += red[w][tid]; s2 += red[w + 8][tid]; }
            atomicAdd(&g_dsum[stage][n0 + tid], s);
            atomicAdd(&g_dsum2[stage][n0 + tid], s2);
        }
    }
}

// ================= symmetric dist, pipelined, A un-duplicated =================
__global__ __launch_bounds__(256, 2)
void dist_kernel(const float* __restrict__ key, const float* __restrict__ sq,
                 float* __restrict__ dist)
{
    int b = blockIdx.z;
    const float* A  = key + (size_t)b * NPTS * C_;
    const float* sb = sq + b * NPTS;
    float* D = dist + (size_t)b * NPTS * NPTS;

    int t = blockIdx.x, bi = 0;
    while (t >= 16 - bi) { t -= 16 - bi; bi++; }
    int bj = bi + t;

    __shared__ __align__(16) float Asq[2][16][128];
    __shared__ __align__(16) float Wt[2][16][128];
    int tid = threadIdx.x;
    int tx = tid & 15, ty = tid >> 4;
    int m0 = bi * 128, n0 = bj * 128;
    int lr = tid >> 2;
    int lc = (tid & 3) << 2;

    int wf0 = (q32(lr >> 2) << 2) | (lr & 3);
    int wf1 = (q32((lr + 64) >> 2) << 2) | (lr & 3);
    int ra0 = q32(2 * ty) << 2;
    int ra1 = q32(2 * ty + 1) << 2;
    int qw0 = q32(2 * tx) << 2;
    int qw1 = q32(2 * tx + 1) << 2;

    ull acc[8][4] = {};
    float4 a0, a1, w0, w1;

#define D_STS(BF) { \
        Asq[BF][lc+0][wf0] = a0.x; Asq[BF][lc+1][wf0] = a0.y; \
        Asq[BF][lc+2][wf0] = a0.z; Asq[BF][lc+3][wf0] = a0.w; \
        Asq[BF][lc+0][wf1] = a1.x; Asq[BF][lc+1][wf1] = a1.y; \
        Asq[BF][lc+2][wf1] = a1.z; Asq[BF][lc+3][wf1] = a1.w; \
        Wt[BF][lc+0][wf0] = w0.x; Wt[BF][lc+1][wf0] = w0.y; \
        Wt[BF][lc+2][wf0] = w0.z; Wt[BF][lc+3][wf0] = w0.w; \
        Wt[BF][lc+0][wf1] = w1.x; Wt[BF][lc+1][wf1] = w1.y; \
        Wt[BF][lc+2][wf1] = w1.z; Wt[BF][lc+3][wf1] = w1.w; }

    a0 = *(const float4*)&A[(size_t)(m0 + lr)      * C_ + lc];
    a1 = *(const float4*)&A[(size_t)(m0 + lr + 64) * C_ + lc];
    w0 = *(const float4*)&A[(size_t)(n0 + lr)      * C_ + lc];
    w1 = *(const float4*)&A[(size_t)(n0 + lr + 64) * C_ + lc];
    D_STS(0)
    __syncthreads();

    const int nT = C_ >> 4;
    for (int it = 0; it < nT; it++) {
        int cur = it & 1;
        if (it + 1 < nT) {
            int k0 = (it + 1) << 4;
            a0 = *(const float4*)&A[(size_t)(m0 + lr)      * C_ + k0 + lc];
            a1 = *(const float4*)&A[(size_t)(m0 + lr + 64) * C_ + k0 + lc];
            w0 = *(const float4*)&A[(size_t)(n0 + lr)      * C_ + k0 + lc];
            w1 = *(const float4*)&A[(size_t)(n0 + lr + 64) * C_ + k0 + lc];
        }
        #pragma unroll
        for (int kk = 0; kk < 16; kk++) MAIN_FMA(Asq[cur], Wt[cur])
        if (it + 1 < nT) {
            int nb = cur ^ 1;
            __syncthreads();
            { int BF = nb; D_STS(BF) }
            __syncthreads();
        }
    }
#undef D_STS

    float f[8][8];
    #pragma unroll
    for (int i = 0; i < 8; i++)
        #pragma unroll
        for (int j = 0; j < 4; j++) {
            float2 p = unpk(acc[i][j]);
            f[i][2*j] = p.x; f[i][2*j+1] = p.y;
        }

    float sn[8], sm[8];
    *(float4*)(sn)     = *(const float4*)&sb[n0 + tx*8];
    *(float4*)(sn + 4) = *(const float4*)&sb[n0 + tx*8 + 4];
    *(float4*)(sm)     = *(const float4*)&sb[m0 + ty*8];
    *(float4*)(sm + 4) = *(const float4*)&sb[m0 + ty*8 + 4];

    #pragma unroll
    for (int i = 0; i < 8; i++) {
        float o[8];
        #pragma unroll
        for (int j = 0; j < 8; j++) o[j] = sm[i] + sn[j] - 2.f * f[i][j];
        size_t r = (size_t)(m0 + ty*8 + i) * NPTS + n0 + tx*8;
        *(float4*)&D[r]     = *(float4*)(o);
        *(float4*)&D[r + 4] = *(float4*)(o + 4);
    }
    if (bi != bj) {
        #pragma unroll
        for (int j = 0; j < 8; j++) {
            float o[8];
            #pragma unroll
            for (int i = 0; i < 8; i++) o[i] = sn[j] + sm[i] - 2.f * f[i][j];
            size_t r = (size_t)(n0 + tx*8 + j) * NPTS + m0 + ty*8;
            *(float4*)&D[r]     = *(float4*)(o);
            *(float4*)&D[r + 4] = *(float4*)(o + 4);
        }
    }
}

// ---------------- BN apply q/k/v + fused sq ----------------
__global__ __launch_bounds__(256)
void bnqkv_kernel(const float* __restrict__ Y, float* __restrict__ out,
                  const float* __restrict__ gq, const float* __restrict__ bq,
                  const float* __restrict__ gk, const float* __restrict__ bk,
                  const float* __restrict__ gv, const float* __restrict__ bv,
                  float* __restrict__ sqv)
{
    int blk = blockIdx.x;
    int slice = blk >> 12;
    int row   = blk & 4095;
    int d = threadIdx.x;
    const float* gamma = slice == 0 ? gq : slice == 1 ? gk : gv;
    const float* beta  = slice == 0 ? bq : slice == 1 ? bk : bv;
    float a, c;
    foldco(slice, d, INV_M1, gamma, beta, a, c);
    size_t e = (size_t)blk * 256 + d;
    float z = a * Y[e] + c;
    float o = lrelu(z);
    out[e] = o;

    if (slice == 1) {
        __shared__ float sh[8];
        float s = o * o;
        #pragma unroll
        for (int off = 16; off; off >>= 1) s += __shfl_down_sync(0xffffffffu, s, off);
        if ((d & 31) == 0) sh[d >> 5] = s;
        __syncthreads();
        if (d == 0) {
            float t = 0.f;
            #pragma unroll
            for (int w = 0; w < 8; w++) t += sh[w];
            sqv[row] = t;
        }
    }
}

// ---------------- top-32 ----------------
#define CE(i,j) { if (vr[j] < vr[i] || (vr[j] == vr[i] && idr[j] < idr[i])) { \
                    float tv = vr[i]; vr[i] = vr[j]; vr[j] = tv; \
                    int ti = idr[i]; idr[i] = idr[j]; idr[j] = ti; } }

__global__ __launch_bounds__(256)
void topk_kernel(const float* __restrict__ dist)
{
    int bn = blockIdx.x;
    const float* row = dist + (size_t)bn * NPTS;
    int t = threadIdx.x;
    int lane = t & 31, wrp = t >> 5;

    __shared__ float lv[8][32];
    __shared__ int   li[8][32];

    {
        float vr[8]; int idr[8];
        #pragma unroll
        for (int s = 0; s < 8; s++) {
            int j = wrp * 256 + s * 32 + lane;
            vr[s] = row[j]; idr[s] = j;
        }
        CE(0,1) CE(2,3) CE(4,5) CE(6,7)
        CE(0,2) CE(1,3) CE(4,6) CE(5,7)
        CE(1,2) CE(5,6)
        CE(0,4) CE(1,5) CE(2,6) CE(3,7)
        CE(2,4) CE(3,5)
        CE(1,2) CE(3,4) CE(5,6)

        float outv = FLT_MAX; int outi = 0x7fffffff;
        for (int sel = 0; sel < KNB; sel++) {
            float cv = vr[0]; int ci = idr[0];
            int myhead = idr[0];
            #pragma unroll
            for (int o = 16; o; o >>= 1) {
                float ov = __shfl_xor_sync(0xffffffffu, cv, o);
                int   oi = __shfl_xor_sync(0xffffffffu, ci, o);
                if (ov < cv || (ov == cv && oi < ci)) { cv = ov; ci = oi; }
            }
            if (lane == sel) { outv = cv; outi = ci; }
            if (myhead == ci) {
                #pragma unroll
                for (int s = 0; s < 7; s++) { vr[s] = vr[s+1]; idr[s] = idr[s+1]; }
                vr[7] = FLT_MAX; idr[7] = 0x7fffffff;
            }
        }
        lv[wrp][lane] = outv;
        li[wrp][lane] = outi;
    }
    __syncthreads();

    if (wrp == 0) {
        float vr[8]; int idr[8];
        #pragma unroll
        for (int j = 0; j < 8; j++) { vr[j] = lv[j][lane]; idr[j] = li[j][lane]; }
        CE(0,1) CE(2,3) CE(4,5) CE(6,7)
        CE(0,2) CE(1,3) CE(4,6) CE(5,7)
        CE(1,2) CE(5,6)
        CE(0,4) CE(1,5) CE(2,6) CE(3,7)
        CE(2,4) CE(3,5)
        CE(1,2) CE(3,4) CE(5,6)

        for (int sel = 0; sel < KNB; sel++) {
            float cv = vr[0]; int ci = idr[0];
            int myhead = idr[0];
            #pragma unroll
            for (int o = 16; o; o >>= 1) {
                float ov = __shfl_xor_sync(0xffffffffu, cv, o);
                int   oi = __shfl_xor_sync(0xffffffffu, ci, o);
                if (ov < cv || (ov == cv && oi < ci)) { cv = ov; ci = oi; }
            }
            if (lane == 0) g_idx[(size_t)bn * KNB + sel] = ci;
            if (myhead == ci) {
                #pragma unroll
                for (int s = 0; s < 7; s++) { vr[s] = vr[s+1]; idr[s] = idr[s+1]; }
                vr[7] = FLT_MAX; idr[7] = 0x7fffffff;
            }
        }
    }
}

// ---------------- stats infra ----------------
__global__ void zero_all_stats()
{
    int i = blockIdx.x * 256 + threadIdx.x;
    if (i < 8 * HID) { ((double*)g_dsum)[i] = 0.0; ((double*)g_dsum2)[i] = 0.0; }
}

// ---------------- posb stats via moments ----------------
__global__ __launch_bounds__(256)
void pbstats_kernel(const float* __restrict__ P)
{
    int d = threadIdx.x;
    float s = 0.f, s2 = 0.f;
    for (int gidx = 0; gidx < 16; gidx++) {
        int bn = blockIdx.x * 16 + gidx;
        int b  = bn >> 11;
        float pn = P[(size_t)bn * C_ + d];
        const int* ip = &g_idx[(size_t)bn * KNB];
        float A1 = 0.f, A2 = 0.f;
        #pragma unroll 4
        for (int k = 0; k < KNB; k++) {
            int jg = (b << 11) + ip[k];
            float v = P[(size_t)jg * C_ + d];
            A1 += v; A2 += v * v;
        }
        s  += A1 - 32.f * pn;
        s2 += A2 - 2.f * pn * A1 + 32.f * pn * pn;
    }
    atomicAdd(&g_dsum[ST_PB][d],  (double)s);
    atomicAdd(&g_dsum2[ST_PB][d], (double)s2);
}

// ---------------- final BN+silu+residual ----------------
__global__ void bn_silu_res_apply(const float* __restrict__ Y, const float* __restrict__ res,
                                  float* __restrict__ out,
                                  const float* __restrict__ gm2, const float* __restrict__ bm2)
{
    int d = threadIdx.x;
    float a, c;
    foldco(ST_M2, d, INV_M1, gm2, bm2, a, c);
    size_t e = (size_t)blockIdx.x * 256 + d;
    float z = a * Y[e] + c;
    out[e] = res[e] + z / (1.f + expf(-z));
}

// ---------------- vec1: PIPELINED gather GEMM ----------------
__global__ __launch_bounds__(256)
void vec1_kernel(const float* __restrict__ qb, const float* __restrict__ kb,
                 const float* __restrict__ P,  const float* __restrict__ We1,
                 const float* __restrict__ gpb, const float* __restrict__ bpb,
                 float* __restrict__ s1)
{
    __shared__ __align__(16) float As[2][16][128];
    __shared__ __align__(16) float Wsd[2][16][64];
    __shared__ __align__(16) float spa[C_], spc[C_];
    __shared__ int sj[128];
    __shared__ float cs[8][32], cs2[8][32];
    int tid = threadIdx.x;
    int m0 = blockIdx.x * 128;
    foldco(ST_PB, tid, INV_M2, gpb, bpb, spa[tid], spc[tid]);
    if (tid < 128) sj[tid] = g_idx[m0 + tid];
    __syncthreads();

    int tx = tid & 15, ty = tid >> 4;
    int lr = tid >> 2;
    int lc = (tid & 3) << 2;
    int r0 = m0 + lr,      bn0 = r0 >> 5, b0 = r0 >> 16;
    int r1 = m0 + lr + 64, bn1 = r1 >> 5, b1 = r1 >> 16;
    int jg0 = (b0 << 11) + sj[lr];
    int jg1 = (b1 << 11) + sj[lr + 64];
    ull acc[4][2] = {};

    float4 kf0, qf0, pj0, pn0, kf1, qf1, pj1, pn1;
    float ws0, ws1;

#define V_LOAD(K0) { \
        kf0 = *(const float4*)&kb[(size_t)jg0 * C_ + (K0) + lc]; \
        qf0 = *(const float4*)&qb[(size_t)bn0 * C_ + (K0) + lc]; \
        pj0 = *(const float4*)&P [(size_t)jg0 * C_ + (K0) + lc]; \
        pn0 = *(const float4*)&P [(size_t)bn0 * C_ + (K0) + lc]; \
        kf1 = *(const float4*)&kb[(size_t)jg1 * C_ + (K0) + lc]; \
        qf1 = *(const float4*)&qb[(size_t)bn1 * C_ + (K0) + lc]; \
        pj1 = *(const float4*)&P [(size_t)jg1 * C_ + (K0) + lc]; \
        pn1 = *(const float4*)&P [(size_t)bn1 * C_ + (K0) + lc]; \
        ws0 = We1[(size_t)(tid & 31) * C_ + (K0) + (tid >> 5)]; \
        ws1 = We1[(size_t)(tid & 31) * C_ + (K0) + (tid >> 5) + 8]; }
#define V_STS(BF, K0) { \
        float4 pa = *(const float4*)&spa[(K0) + lc]; \
        float4 pc = *(const float4*)&spc[(K0) + lc]; \
        As[BF][lc+0][lr] = kf0.x - qf0.x + lrelu(pa.x * (pj0.x - pn0.x) + pc.x); \
        As[BF][lc+1][lr] = kf0.y - qf0.y + lrelu(pa.y * (pj0.y - pn0.y) + pc.y); \
        As[BF][lc+2][lr] = kf0.z - qf0.z + lrelu(pa.z * (pj0.z - pn0.z) + pc.z); \
        As[BF][lc+3][lr] = kf0.w - qf0.w + lrelu(pa.w * (pj0.w - pn0.w) + pc.w); \
        As[BF][lc+0][lr+64] = kf1.x - qf1.x + lrelu(pa.x * (pj1.x - pn1.x) + pc.x); \
        As[BF][lc+1][lr+64] = kf1.y - qf1.y + lrelu(pa.y * (pj1.y - pn1.y) + pc.y); \
        As[BF][lc+2][lr+64] = kf1.z - qf1.z + lrelu(pa.z * (pj1.z - pn1.z) + pc.z); \
        As[BF][lc+3][lr+64] = kf1.w - qf1.w + lrelu(pa.w * (pj1.w - pn1.w) + pc.w); \
        *(ull*)&Wsd[BF][tid >> 5][2*(tid & 31)]       = dup2(ws0); \
        *(ull*)&Wsd[BF][(tid >> 5) + 8][2*(tid & 31)] = dup2(ws1); }

    V_LOAD(0)
    V_STS(0, 0)
    __syncthreads();
    const int nT = C_ >> 4;
    for (int it = 0; it < nT; it++) {
        int cur = it & 1;
        if (it + 1 < nT) V_LOAD((it + 1) << 4)
        #pragma unroll
        for (int kk = 0; kk < 16; kk++) {
            ulonglong2 aA = *(const ulonglong2*)&As[cur][kk][ty*8];
            ulonglong2 aB = *(const ulonglong2*)&As[cur][kk][ty*8 + 4];
            ull ap[4] = { aA.x, aA.y, aB.x, aB.y };
            ulonglong2 wv = *(const ulonglong2*)&Wsd[cur][kk][4*tx];
            #pragma unroll
            for (int i2 = 0; i2 < 4; i2++) {
                fma2(acc[i2][0], ap[i2], wv.x);
                fma2(acc[i2][1], ap[i2], wv.y);
            }
        }
        if (it + 1 < nT) {
            __syncthreads();
            V_STS(cur ^ 1, (it + 1) << 4)
            __syncthreads();
        }
    }
#undef V_LOAD
#undef V_STS

    #pragma unroll
    for (int i2 = 0; i2 < 4; i2++) {
        float2 p0 = unpk(acc[i2][0]), p1 = unpk(acc[i2][1]);
        size_t w0 = (size_t)(m0 + ty*8 + 2*i2) * CPH + tx*2;
        s1[w0]           = p0.x; s1[w0 + 1]       = p1.x;
        s1[w0 + CPH]     = p0.y; s1[w0 + CPH + 1] = p1.y;
    }
    float ps[2], ps2[2];
    #pragma unroll
    for (int j = 0; j < 2; j++) {
        ull s = add2(add2(acc[0][j], acc[1][j]), add2(acc[2][j], acc[3][j]));
        ull q = add2(add2(mul2(acc[0][j], acc[0][j]), mul2(acc[1][j], acc[1][j])),
                     add2(mul2(acc[2][j], acc[2][j]), mul2(acc[3][j], acc[3][j])));
        float2 fs = unpk(s), fq = unpk(q);
        ps[j] = fs.x + fs.y; ps2[j] = fq.x + fq.y;
    }
    ps[0]  += __shfl_down_sync(0xffffffffu, ps[0], 16);
    ps[1]  += __shfl_down_sync(0xffffffffu, ps[1], 16);
    ps2[0] += __shfl_down_sync(0xffffffffu, ps2[0], 16);
    ps2[1] += __shfl_down_sync(0xffffffffu, ps2[1], 16);
    int lane = tid & 31, wrp = tid >> 5;
    if (lane < 16) {
        cs[wrp][tx*2]      = ps[0];  cs[wrp][tx*2 + 1]  = ps[1];
        cs2[wrp][tx*2]     = ps2[0]; cs2[wrp][tx*2 + 1] = ps2[1];
    }
    __syncthreads();
    if (tid < 32) {
        double s = 0.0, s2 = 0.0;
        #pragma unroll
        for (int w = 0; w < 8; w++) { s += cs[w][tid]; s2 += cs2[w][tid]; }
        atomicAdd(&g_dsum[ST_S1][tid], s);
        atomicAdd(&g_dsum2[ST_S1][tid], s2);
    }
}

// ---------------- vec2 ----------------
__global__ __launch_bounds__(256)
void vec2_kernel(const float* __restrict__ s1, const float* __restrict__ We2,
                 const float* __restrict__ ge1, const float* __restrict__ be1,
                 float* __restrict__ s2)
{
    __shared__ __align__(16) float As[16][128];
    __shared__ __align__(16) float Wsd[16][64];
    __shared__ __align__(16) float sfa[CPH], sfc[CPH];
    __shared__ float cs[8][32], cs2[8][32];
    int tid = threadIdx.x;
    int m0 = blockIdx.x * 128;
    if (tid < CPH) foldco(ST_S1, tid, INV_M2, ge1, be1, sfa[tid], sfc[tid]);
    __syncthreads();

    int tx = tid & 15, ty = tid >> 4;
    int lr = tid >> 2;
    int lc = (tid & 3) << 2;
    ull acc[4][2] = {};

    for (int k0 = 0; k0 < CPH; k0 += 16) {
        #pragma unroll
        for (int h = 0; h < 2; h++) {
            int rr = h ? lr + 64 : lr;
            float4 y  = *(const float4*)&s1[(size_t)(m0 + rr) * CPH + k0 + lc];
            float4 aa = *(const float4*)&sfa[k0 + lc];
            float4 cc = *(const float4*)&sfc[k0 + lc];
            As[lc+0][rr] = lrelu(aa.x * y.x + cc.x);
            As[lc+1][rr] = lrelu(aa.y * y.y + cc.y);
            As[lc+2][rr] = lrelu(aa.z * y.z + cc.z);
            As[lc+3][rr] = lrelu(aa.w * y.w + cc.w);
        }
        {
            int i0 = tid;
            *(ull*)&Wsd[i0 >> 5][2*(i0 & 31)] = dup2(We2[(size_t)(i0 & 31) * CPH + k0 + (i0 >> 5)]);
            int i1 = tid + 256;
            *(ull*)&Wsd[i1 >> 5][2*(i1 & 31)] = dup2(We2[(size_t)(i1 & 31) * CPH + k0 + (i1 >> 5)]);
        }
        __syncthreads();
        #pragma unroll
        for (int kk = 0; kk < 16; kk++) {
            ulonglong2 aA = *(const ulonglong2*)&As[kk][ty*8];
            ulonglong2 aB = *(const ulonglong2*)&As[kk][ty*8 + 4];
            ull ap[4] = { aA.x, aA.y, aB.x, aB.y };
            ulonglong2 wv = *(const ulonglong2*)&Wsd[kk][4*tx];
            #pragma unroll
            for (int i2 = 0; i2 < 4; i2++) {
                fma2(acc[i2][0], ap[i2], wv.x);
                fma2(acc[i2][1], ap[i2], wv.y);
            }
        }
        __syncthreads();
    }
    #pragma unroll
    for (int i2 = 0; i2 < 4; i2++) {
        float2 p0 = unpk(acc[i2][0]), p1 = unpk(acc[i2][1]);
        size_t w0 = (size_t)(m0 + ty*8 + 2*i2) * CPH + tx*2;
        s2[w0]           = p0.x; s2[w0 + 1]       = p1.x;
        s2[w0 + CPH]     = p0.y; s2[w0 + CPH + 1] = p1.y;
    }
    float ps[2], ps2[2];
    #pragma unroll
    for (int j = 0; j < 2; j++) {
        ull s = add2(add2(acc[0][j], acc[1][j]), add2(acc[2][j], acc[3][j]));
        ull q = add2(add2(mul2(acc[0][j], acc[0][j]), mul2(acc[1][j], acc[1][j])),
                     add2(mul2(acc[2][j], acc[2][j]), mul2(acc[3][j], acc[3][j])));
        float2 fs = unpk(s), fq = unpk(q);
        ps[j] = fs.x + fs.y; ps2[j] = fq.x + fq.y;
    }
    ps[0]  += __shfl_down_sync(0xffffffffu, ps[0], 16);
    ps[1]  += __shfl_down_sync(0xffffffffu, ps[1], 16);
    ps2[0] += __shfl_down_sync(0xffffffffu, ps2[0], 16);
    ps2[1] += __shfl_down_sync(0xffffffffu, ps2[1], 16);
    int lane = tid & 31, wrp = tid >> 5;
    if (lane < 16) {
        cs[wrp][tx*2]      = ps[0];  cs[wrp][tx*2 + 1]  = ps[1];
        cs2[wrp][tx*2]     = ps2[0]; cs2[wrp][tx*2 + 1] = ps2[1];
    }
    __syncthreads();
    if (tid < 32) {
        double s = 0.0, s2 = 0.0;
        #pragma unroll
        for (int w = 0; w < 8; w++) { s += cs[w][tid]; s2 += cs2[w][tid]; }
        atomicAdd(&g_dsum[ST_S2][tid], s);
        atomicAdd(&g_dsum2[ST_S2][tid], s2);
    }
}

// ---------------- attention ----------------
__global__ __launch_bounds__(256)
void attn_kernel(const float* __restrict__ x, const float* __restrict__ s2,
                 const float* __restrict__ vb, const float* __restrict__ P,
                 const float* __restrict__ ge2, const float* __restrict__ be2,
                 const float* __restrict__ gpb, const float* __restrict__ bpb,
                 float* __restrict__ xattn)
{
    int bn = blockIdx.x;
    int t = threadIdx.x;
    __shared__ float soft[KNB][CPH + 1];
    __shared__ float ssa[CPH], ssc[CPH];
    __shared__ int sj[KNB];
    if (t < CPH) foldco(ST_S2, t, INV_M2, ge2, be2, ssa[t], ssc[t]);
    if (t >= 32 && t < 64) sj[t - 32] = g_idx[(size_t)bn * KNB + t - 32];
    float pa, pc;
    foldco(ST_PB, t, INV_M2, gpb, bpb, pa, pc);
    __syncthreads();

    size_t base = (size_t)bn * KNB * CPH;
    for (int e = t; e < KNB * CPH; e += 256) {
        int g = e & 31;
        float y = s2[base + e];
        soft[e >> 5][g] = lrelu(ssa[g] * y + ssc[g]);
    }
    __syncthreads();
    if (t < CPH) {
        float mx = -FLT_MAX;
        #pragma unroll
        for (int k = 0; k < KNB; k++) mx = fmaxf(mx, soft[k][t]);
        float s = 0.f;
        #pragma unroll
        for (int k = 0; k < KNB; k++) { float ev = expf(soft[k][t] - mx); soft[k][t] = ev; s += ev; }
        float inv = 1.f / s;
        #pragma unroll
        for (int k = 0; k < KNB; k++) soft[k][t] *= inv;
    }
    __syncthreads();

    int c = t, g = t >> 3;
    int b = bn >> 11;
    float pn = P[(size_t)bn * C_ + c];
    float acc = 0.f;
    #pragma unroll
    for (int k = 0; k < KNB; k++) {
        int jg = (b << 11) + sj[k];
        float posb = lrelu(pa * (P[(size_t)jg * C_ + c] - pn) + pc);
        acc += (vb[(size_t)jg * C_ + c] + posb) * soft[k][g];
    }
    size_t o = (size_t)bn * C_ + c;
    xattn[o] = x[o] + acc;
}

extern "C" void kernel_launch(void* const* d_in, const int* in_sizes, int n_in,
                              void* d_out, int out_size)
{
    const float* x   = (const float*)d_in[0];
    const float* pos = (const float*)d_in[1];
    const float* Wq  = (const float*)d_in[2];
    const float* gq  = (const float*)d_in[3];
    const float* bq  = (const float*)d_in[4];
    const float* Wk  = (const float*)d_in[5];
    const float* gk  = (const float*)d_in[6];
    const float* bk  = (const float*)d_in[7];
    const float* Wv  = (const float*)d_in[8];
    const float* gv  = (const float*)d_in[9];
    const float* bv  = (const float*)d_in[10];
    const float* Wpb = (const float*)d_in[11];
    const float* gpb = (const float*)d_in[12];
    const float* bpb = (const float*)d_in[13];
    const float* We1 = (const float*)d_in[14];
    const float* ge1 = (const float*)d_in[15];
    const float* be1 = (const float*)d_in[16];
    const float* We2 = (const float*)d_in[17];
    const float* ge2 = (const float*)d_in[18];
    const float* be2 = (const float*)d_in[19];
    const float* Wm1 = (const float*)d_in[20];
    const float* gm1 = (const float*)d_in[21];
    const float* bm1 = (const float*)d_in[22];
    const float* Wm2 = (const float*)d_in[23];
    const float* gm2 = (const float*)d_in[24];
    const float* bm2 = (const float*)d_in[25];
    float* out = (float*)d_out;

    void* p;
    float *qkv, *tmp, *sqv, *dist, *s1, *s2, *xatt;
    cudaGetSymbolAddress(&p, g_qkv);   qkv  = (float*)p;
    cudaGetSymbolAddress(&p, g_tmp4);  tmp  = (float*)p;
    cudaGetSymbolAddress(&p, g_sqv);   sqv  = (float*)p;
    cudaGetSymbolAddress(&p, g_dist);  dist = (float*)p;
    cudaGetSymbolAddress(&p, g_s1);    s1   = (float*)p;
    cudaGetSymbolAddress(&p, g_s2);    s2   = (float*)p;
    cudaGetSymbolAddress(&p, g_xattn); xatt = (float*)p;

    const size_t SL = (size_t)M1 * C_;
    float* t0 = tmp;
    float* t1 = tmp + SL;
    float* t2 = tmp + 2*SL;
    float* t3 = tmp + 3*SL;
    float* qb = qkv;
    float* kb = qkv + SL;
    float* vb = qkv + 2*SL;

    zero_all_stats<<<16, 256>>>();
    {
        Gemm4 g = { { x, x, x, pos }, { Wq, Wk, Wv, Wpb }, { t0, t1, t2, t3 },
                    { ST_Q, ST_K, ST_V, -1 } };
        gemm128p_kernel<<<dim3(C_/128, M1/128, 4), 256>>>(g, C_, C_);
    }
    bnqkv_kernel<<<3 * M1, 256>>>(tmp, qkv, gq, bq, gk, bk, gv, bv, sqv);
    dist_kernel<<<dim3(136, 1, B_), 256>>>(kb, sqv, dist);
    topk_kernel<<<M1, 256>>>(dist);
    pbstats_kernel<<<256, 256>>>(t3);
    vec1_kernel<<<M2/128, 256>>>(qb, kb, t3, We1, gpb, bpb, s1);
    vec2_kernel<<<M2/128, 256>>>(s1, We2, ge1, be1, s2);
    attn_kernel<<<M1, 256>>>(x, s2, vb, t3, ge2, be2, gpb, bpb, xatt);
    {
        Gemm4 g = { { xatt, 0, 0, 0 }, { Wm1, 0, 0, 0 }, { t0, 0, 0, 0 },
                    { ST_M1, -1, -1, -1 } };
        gemm128p_kernel<<<dim3(HID/128, M1/128, 1), 256>>>(g, HID, C_);
    }
    {
        Gemm4 g = { { t0, 0, 0, 0 }, { Wm2, 0, 0, 0 }, { t2, 0, 0, 0 },
                    { ST_M2, -1, -1, -1 } };
        gemm128_kernel<<<dim3(C_/128, M1/128, 1), 256>>>(g, C_, HID, 1, gm1, bm1);
    }
    bn_silu_res_apply<<<M1, 256>>>(t2, xatt, out, gm2, bm2);
}